// round 2
// baseline (speedup 1.0000x reference)
#include <cuda_runtime.h>
#include <cuda_bf16.h>

#define NN   100000
#define EE   600000
#define ETOT 700000          // EE + NN self loops
#define DD   128
#define HH   4
#define FF   32
#define NB4  (NN*4)

// ---------------- scratch (static device allocations; no runtime alloc) ----
__device__ float g_bufA[NN*DD];
__device__ float g_bufB[NN*DD];
__device__ float g_h[NN*DD];
__device__ float g_el[NB4];
__device__ float g_er[NB4];
__device__ float g_invs[NB4];
__device__ float g_e[ETOT*4];
__device__ int   g_deg[NN];
__device__ int   g_off[NN];
__device__ int   g_cur[NN];
__device__ int   g_bsum[128];
__device__ int   g_csrc[ETOT];
__device__ float g_c[DD];
__device__ float g_d[DD];
__device__ float g_cl[HH], g_dl[HH], g_cr[HH], g_dr[HH];

// ---------------- f32x2 packed helpers ------------------------------------
__device__ __forceinline__ unsigned long long pk2(float x, float y){
    unsigned long long r;
    asm("mov.b64 %0, {%1, %2};" : "=l"(r) : "f"(x), "f"(y));
    return r;
}
__device__ __forceinline__ void upk2(unsigned long long v, float& x, float& y){
    asm("mov.b64 {%0, %1}, %2;" : "=f"(x), "=f"(y) : "l"(v));
}
__device__ __forceinline__ unsigned long long ffma2(unsigned long long a,
                                                    unsigned long long b,
                                                    unsigned long long c){
    unsigned long long d;
    asm("fma.rn.f32x2 %0, %1, %2, %3;" : "=l"(d) : "l"(a), "l"(b), "l"(c));
    return d;
}

// ---------------- CSR build ------------------------------------------------
__global__ void k_init_deg(){
    int i = blockIdx.x*blockDim.x + threadIdx.x;
    if (i < NN) g_deg[i] = 1;                 // self loop
}

__global__ void k_hist(const int* __restrict__ dst){
    int i = blockIdx.x*blockDim.x + threadIdx.x;
    if (i < EE) atomicAdd(&g_deg[dst[i]], 1);
}

__global__ void k_scan1(){                    // per-1024-block sums of deg
    int i = blockIdx.x*1024 + threadIdx.x;
    int v = (i < NN) ? g_deg[i] : 0;
    __shared__ int sh[32];
    int lane = threadIdx.x & 31, wd = threadIdx.x >> 5;
    #pragma unroll
    for (int o = 16; o; o >>= 1) v += __shfl_down_sync(0xffffffffu, v, o);
    if (lane == 0) sh[wd] = v;
    __syncthreads();
    if (wd == 0){
        int s = sh[lane];
        #pragma unroll
        for (int o = 16; o; o >>= 1) s += __shfl_down_sync(0xffffffffu, s, o);
        if (lane == 0) g_bsum[blockIdx.x] = s;
    }
}

__global__ void k_scan2(){                    // exclusive scan of 98 block sums
    const int NBK = 98;
    int t = threadIdx.x;                      // 128 threads
    int v = (t < NBK) ? g_bsum[t] : 0;
    int orig = v;
    int lane = t & 31, wd = t >> 5;
    #pragma unroll
    for (int o = 1; o < 32; o <<= 1){
        int u = __shfl_up_sync(0xffffffffu, v, o);
        if (lane >= o) v += u;
    }
    __shared__ int sh[4];
    if (lane == 31) sh[wd] = v;
    __syncthreads();
    int add = 0;
    for (int w = 0; w < wd; w++) add += sh[w];
    if (t < NBK) g_bsum[t] = v - orig + add;
}

__global__ void k_scan3(){                    // per-block exclusive scan + base
    int i = blockIdx.x*1024 + threadIdx.x;
    int v = (i < NN) ? g_deg[i] : 0;
    int orig = v;
    int lane = threadIdx.x & 31, wd = threadIdx.x >> 5;
    #pragma unroll
    for (int o = 1; o < 32; o <<= 1){
        int u = __shfl_up_sync(0xffffffffu, v, o);
        if (lane >= o) v += u;
    }
    __shared__ int sh[32];
    if (lane == 31) sh[wd] = v;
    __syncthreads();
    if (wd == 0){
        int s = sh[lane];
        #pragma unroll
        for (int o = 1; o < 32; o <<= 1){
            int u = __shfl_up_sync(0xffffffffu, s, o);
            if (lane >= o) s += u;
        }
        sh[lane] = s;
    }
    __syncthreads();
    int add = ((wd > 0) ? sh[wd-1] : 0) + g_bsum[blockIdx.x];
    int excl = v - orig + add;
    if (i < NN){ g_off[i] = excl; g_cur[i] = excl; }
}

__global__ void k_fill(const int* __restrict__ src, const int* __restrict__ dst){
    int i = blockIdx.x*blockDim.x + threadIdx.x;
    if (i < EE){
        int d = dst[i];
        int pos = atomicAdd(&g_cur[d], 1);
        g_csrc[pos] = src[i];
    } else if (i < ETOT){
        int n = i - EE;
        int pos = atomicAdd(&g_cur[n], 1);
        g_csrc[pos] = n;
    }
}

// ---------------- layer 0 (rank-1) ----------------------------------------
__global__ void k_l0prep(const float* __restrict__ linW, const float* __restrict__ linb,
                         const float* __restrict__ W0,
                         const float* __restrict__ al0, const float* __restrict__ ar0){
    int j = threadIdx.x;                      // 128 threads, 1 block
    float c = 0.f, d = 0.f;
    const float* wr = W0 + j*DD;
    #pragma unroll 8
    for (int k = 0; k < DD; k++){
        float w = wr[k];
        c += linW[k]*w;
        d += linb[k]*w;
    }
    g_c[j] = c; g_d[j] = d;
    float alv = al0[j], arv = ar0[j];
    float cl = c*alv, dl = d*alv, cr = c*arv, dr = d*arv;
    #pragma unroll
    for (int o = 16; o; o >>= 1){
        cl += __shfl_down_sync(0xffffffffu, cl, o);
        dl += __shfl_down_sync(0xffffffffu, dl, o);
        cr += __shfl_down_sync(0xffffffffu, cr, o);
        dr += __shfl_down_sync(0xffffffffu, dr, o);
    }
    int lane = j & 31, hd = j >> 5;
    if (lane == 0){ g_cl[hd]=cl; g_dl[hd]=dl; g_cr[hd]=cr; g_dr[hd]=dr; }
}

__global__ void k_l0_eler(const float* __restrict__ weights){
    int tid = blockIdx.x*blockDim.x + threadIdx.x;
    if (tid >= NB4) return;
    int n = tid >> 2, h = tid & 3;
    float w = weights[n];
    g_el[tid] = w*g_cl[h] + g_dl[h];
    g_er[tid] = w*g_cr[h] + g_dr[h];
}

// ---------------- GEMM + attention logits (layers 1,2) ---------------------
#define GR 16
__global__ void k_gemm(const float* __restrict__ xin, const float* __restrict__ W,
                       const float* __restrict__ al, const float* __restrict__ ar){
    __shared__ float sx[GR][DD];
    int t = threadIdx.x;                      // 0..127 -> output column j
    int row0 = blockIdx.x * GR;
    #pragma unroll
    for (int r = 0; r < GR; r++){
        float v = xin[(row0 + r)*DD + t];
        v = (v >= 0.f) ? v : 0.01f*v;         // leaky between layers
        sx[r][t] = v;
    }
    __syncthreads();

    unsigned long long acc[GR];
    unsigned long long z = pk2(0.f, 0.f);
    #pragma unroll
    for (int r = 0; r < GR; r++) acc[r] = z;

    const float2* W2 = (const float2*)(W + t*DD);
    #pragma unroll 4
    for (int k2 = 0; k2 < DD/2; k2++){
        float2 wv = W2[k2];
        unsigned long long w2 = pk2(wv.x, wv.y);
        #pragma unroll
        for (int r = 0; r < GR; r++){
            float2 xv = ((const float2*)sx[r])[k2];
            acc[r] = ffma2(w2, pk2(xv.x, xv.y), acc[r]);
        }
    }

    float alv = al[t], arv = ar[t];
    int lane = t & 31, hd = t >> 5;
    #pragma unroll
    for (int r = 0; r < GR; r++){
        float px, py; upk2(acc[r], px, py);
        float hv = px + py;
        int n = row0 + r;
        g_h[n*DD + t] = hv;
        float evl = hv*alv, evr = hv*arv;
        #pragma unroll
        for (int o = 16; o; o >>= 1){
            evl += __shfl_down_sync(0xffffffffu, evl, o);
            evr += __shfl_down_sync(0xffffffffu, evr, o);
        }
        if (lane == 0){ g_el[n*4 + hd] = evl; g_er[n*4 + hd] = evr; }
    }
}

// ---------------- edge softmax (per node,head; serial over in-edges) -------
__global__ void k_softmax(){
    int tid = blockIdx.x*blockDim.x + threadIdx.x;
    if (tid >= NB4) return;
    int n = tid >> 2, h = tid & 3;
    float ern = g_er[tid];
    int start = g_off[n], end = start + g_deg[n];
    float mx = -3.0e38f;
    for (int p = start; p < end; p++){
        float e = g_el[g_csrc[p]*4 + h] + ern;
        e = (e >= 0.f) ? e : 0.2f*e;
        g_e[p*4 + h] = e;
        mx = fmaxf(mx, e);
    }
    float sum = 0.f;
    for (int p = start; p < end; p++){
        float a = __expf(g_e[p*4 + h] - mx);
        g_e[p*4 + h] = a;
        sum += a;
    }
    g_invs[tid] = 1.0f / sum;
}

// ---------------- aggregation: warp per dst node ---------------------------
__global__ void k_aggr(const float* __restrict__ bias, float* __restrict__ out){
    int wid = (blockIdx.x*blockDim.x + threadIdx.x) >> 5;
    if (wid >= NN) return;
    int lane = threadIdx.x & 31;
    int head = lane >> 3;
    float invs = g_invs[wid*4 + head];
    float4 acc = *(const float4*)&bias[lane*4];
    int start = g_off[wid], end = start + g_deg[wid];
    for (int p = start; p < end; p++){
        int s = g_csrc[p];
        float w = g_e[p*4 + head] * invs;
        float4 hv = *(const float4*)&g_h[s*DD + lane*4];
        acc.x += hv.x*w; acc.y += hv.y*w; acc.z += hv.z*w; acc.w += hv.w*w;
    }
    *(float4*)&out[wid*DD + lane*4] = acc;
}

// layer-0 variant: h0[src] = weights[src]*c + d  (4B gather instead of 512B)
__global__ void k_aggr0(const float* __restrict__ weights,
                        const float* __restrict__ bias, float* __restrict__ out){
    int wid = (blockIdx.x*blockDim.x + threadIdx.x) >> 5;
    if (wid >= NN) return;
    int lane = threadIdx.x & 31;
    int head = lane >> 3;
    float invs = g_invs[wid*4 + head];
    float4 c4 = *(const float4*)&g_c[lane*4];
    float4 d4 = *(const float4*)&g_d[lane*4];
    float4 acc = *(const float4*)&bias[lane*4];
    int start = g_off[wid], end = start + g_deg[wid];
    for (int p = start; p < end; p++){
        int s = g_csrc[p];
        float ws = weights[s];
        float w = g_e[p*4 + head] * invs;
        acc.x += (ws*c4.x + d4.x)*w;
        acc.y += (ws*c4.y + d4.y)*w;
        acc.z += (ws*c4.z + d4.z)*w;
        acc.w += (ws*c4.w + d4.w)*w;
    }
    *(float4*)&out[wid*DD + lane*4] = acc;
}

// ---------------- final prediction head ------------------------------------
__global__ void k_pred(const float* __restrict__ x, const float* __restrict__ pw,
                       const float* __restrict__ pb, float* __restrict__ out){
    int wid = (blockIdx.x*blockDim.x + threadIdx.x) >> 5;
    if (wid >= NN) return;
    int lane = threadIdx.x & 31;
    float4 xv = *(const float4*)&x[wid*DD + lane*4];
    float4 wv = *(const float4*)&pw[lane*4];
    float s = xv.x*wv.x + xv.y*wv.y + xv.z*wv.z + xv.w*wv.w;
    #pragma unroll
    for (int o = 16; o; o >>= 1) s += __shfl_down_sync(0xffffffffu, s, o);
    if (lane == 0) out[wid] = s + pb[0];
}

// ---------------- launch ----------------------------------------------------
extern "C" void kernel_launch(void* const* d_in, const int* in_sizes, int n_in,
                              void* d_out, int out_size){
    const float* weights = (const float*)d_in[0];
    const float* lin_W   = (const float*)d_in[1];
    const float* lin_b   = (const float*)d_in[2];
    const float* fc_W    = (const float*)d_in[3];
    const float* attn_l  = (const float*)d_in[4];
    const float* attn_r  = (const float*)d_in[5];
    const float* conv_b  = (const float*)d_in[6];
    const float* pred_W  = (const float*)d_in[7];
    const float* pred_b  = (const float*)d_in[8];
    const int*   src     = (const int*)d_in[9];
    const int*   dst     = (const int*)d_in[10];
    float* out = (float*)d_out;

    // pointers to scratch symbols (device globals used directly in kernels)
    // --- CSR build (once per launch) ---
    k_init_deg<<<(NN+255)/256, 256>>>();
    k_hist<<<(EE+255)/256, 256>>>(dst);
    k_scan1<<<98, 1024>>>();
    k_scan2<<<1, 128>>>();
    k_scan3<<<98, 1024>>>();
    k_fill<<<(ETOT+255)/256, 256>>>(src, dst);

    // --- layer 0 (rank-1 features) ---
    k_l0prep<<<1, 128>>>(lin_W, lin_b, fc_W, attn_l, attn_r);
    k_l0_eler<<<(NB4+255)/256, 256>>>(weights);
    k_softmax<<<(NB4+255)/256, 256>>>();
    k_aggr0<<<(NN*32+255)/256, 256>>>(weights, conv_b, g_bufA);

    // --- layer 1 ---
    k_gemm<<<NN/GR, 128>>>(g_bufA, fc_W + 1*DD*DD, attn_l + 1*DD, attn_r + 1*DD);
    k_softmax<<<(NB4+255)/256, 256>>>();
    k_aggr<<<(NN*32+255)/256, 256>>>(conv_b + 1*DD, g_bufB);

    // --- layer 2 ---
    k_gemm<<<NN/GR, 128>>>(g_bufB, fc_W + 2*DD*DD, attn_l + 2*DD, attn_r + 2*DD);
    k_softmax<<<(NB4+255)/256, 256>>>();
    k_aggr<<<(NN*32+255)/256, 256>>>(conv_b + 2*DD, g_bufA);

    // --- prediction head ---
    k_pred<<<(NN*32+255)/256, 256>>>(g_bufA, pred_W, pred_b, out);
}

// round 5
// speedup vs baseline: 4.7046x; 4.7046x over previous
#include <cuda_runtime.h>
#include <cuda_bf16.h>

#define NN   100000
#define NNP  100096          // 782 * 128 (row-padded for GEMM tiles)
#define EE   600000
#define ETOT 700000          // EE + NN self loops
#define DD   128
#define HH   4
#define FF   32
#define NB4  (NN*4)

typedef unsigned long long ull;

// ---------------- scratch: device symbols, used ONLY inside device code ----
__device__ __align__(256) float g_x[NNP*DD];   // current node features
__device__ __align__(256) float g_h[NNP*DD];   // fc output of current layer
__device__ __align__(256) float g_el[NB4];
__device__ __align__(256) float g_er[NB4];
__device__ __align__(256) float g_invs[NB4];
__device__ __align__(256) float g_e[ETOT*4];
__device__ __align__(256) int   g_deg[NN];
__device__ __align__(256) int   g_off[NN];
__device__ __align__(256) int   g_cur[NN];
__device__ __align__(256) int   g_bsum[128];
__device__ __align__(256) int   g_csrc[ETOT];
__device__ __align__(256) float g_c[DD];
__device__ __align__(256) float g_d[DD];
__device__ float g_cl[HH], g_dl[HH], g_cr[HH], g_dr[HH];

// ---------------- f32x2 packed helpers ------------------------------------
__device__ __forceinline__ ull pk2(float x, float y){
    ull r; asm("mov.b64 %0, {%1, %2};" : "=l"(r) : "f"(x), "f"(y)); return r;
}
__device__ __forceinline__ void upk2(ull v, float& x, float& y){
    asm("mov.b64 {%0, %1}, %2;" : "=f"(x), "=f"(y) : "l"(v));
}
__device__ __forceinline__ ull ffma2(ull a, ull b, ull c){
    ull d; asm("fma.rn.f32x2 %0, %1, %2, %3;" : "=l"(d) : "l"(a), "l"(b), "l"(c)); return d;
}

// ---------------- CSR build ------------------------------------------------
__global__ void k_init_deg(){
    int i = blockIdx.x*blockDim.x + threadIdx.x;
    if (i < NN) g_deg[i] = 1;                 // self loop
}

__global__ void k_hist(const int* __restrict__ dst){
    int i = blockIdx.x*blockDim.x + threadIdx.x;
    if (i < EE) atomicAdd(&g_deg[dst[i]], 1);
}

__global__ void k_scan1(){                    // per-1024-block sums of deg
    int i = blockIdx.x*1024 + threadIdx.x;
    int v = (i < NN) ? g_deg[i] : 0;
    __shared__ int sh[32];
    int lane = threadIdx.x & 31, wd = threadIdx.x >> 5;
    #pragma unroll
    for (int o = 16; o; o >>= 1) v += __shfl_down_sync(0xffffffffu, v, o);
    if (lane == 0) sh[wd] = v;
    __syncthreads();
    if (wd == 0){
        int s = sh[lane];
        #pragma unroll
        for (int o = 16; o; o >>= 1) s += __shfl_down_sync(0xffffffffu, s, o);
        if (lane == 0) g_bsum[blockIdx.x] = s;
    }
}

__global__ void k_scan2(){                    // exclusive scan of 98 block sums
    const int NBK = 98;
    int t = threadIdx.x;                      // 128 threads
    int v = (t < NBK) ? g_bsum[t] : 0;
    int orig = v;
    int lane = t & 31, wd = t >> 5;
    #pragma unroll
    for (int o = 1; o < 32; o <<= 1){
        int u = __shfl_up_sync(0xffffffffu, v, o);
        if (lane >= o) v += u;
    }
    __shared__ int sh[4];
    if (lane == 31) sh[wd] = v;
    __syncthreads();
    int add = 0;
    for (int w = 0; w < wd; w++) add += sh[w];
    if (t < NBK) g_bsum[t] = v - orig + add;
}

__global__ void k_scan3(){                    // per-block exclusive scan + base
    int i = blockIdx.x*1024 + threadIdx.x;
    int v = (i < NN) ? g_deg[i] : 0;
    int orig = v;
    int lane = threadIdx.x & 31, wd = threadIdx.x >> 5;
    #pragma unroll
    for (int o = 1; o < 32; o <<= 1){
        int u = __shfl_up_sync(0xffffffffu, v, o);
        if (lane >= o) v += u;
    }
    __shared__ int sh[32];
    if (lane == 31) sh[wd] = v;
    __syncthreads();
    if (wd == 0){
        int s = sh[lane];
        #pragma unroll
        for (int o = 1; o < 32; o <<= 1){
            int u = __shfl_up_sync(0xffffffffu, s, o);
            if (lane >= o) s += u;
        }
        sh[lane] = s;
    }
    __syncthreads();
    int add = ((wd > 0) ? sh[wd-1] : 0) + g_bsum[blockIdx.x];
    int excl = v - orig + add;
    if (i < NN){ g_off[i] = excl; g_cur[i] = excl; }
}

__global__ void k_fill(const int* __restrict__ src, const int* __restrict__ dst){
    int i = blockIdx.x*blockDim.x + threadIdx.x;
    if (i < EE){
        int d = dst[i];
        int pos = atomicAdd(&g_cur[d], 1);
        g_csrc[pos] = src[i];
    } else if (i < ETOT){
        int n = i - EE;
        int pos = atomicAdd(&g_cur[n], 1);
        g_csrc[pos] = n;
    }
}

// ---------------- layer 0 (rank-1) ----------------------------------------
__global__ void k_l0prep(const float* __restrict__ linW, const float* __restrict__ linb,
                         const float* __restrict__ W0,
                         const float* __restrict__ al0, const float* __restrict__ ar0){
    int j = threadIdx.x;                      // 128 threads, 1 block
    float c = 0.f, d = 0.f;
    const float* wr = W0 + j*DD;
    #pragma unroll 8
    for (int k = 0; k < DD; k++){
        float w = wr[k];
        c += linW[k]*w;
        d += linb[k]*w;
    }
    g_c[j] = c; g_d[j] = d;
    float alv = al0[j], arv = ar0[j];
    float cl = c*alv, dl = d*alv, cr = c*arv, dr = d*arv;
    #pragma unroll
    for (int o = 16; o; o >>= 1){
        cl += __shfl_down_sync(0xffffffffu, cl, o);
        dl += __shfl_down_sync(0xffffffffu, dl, o);
        cr += __shfl_down_sync(0xffffffffu, cr, o);
        dr += __shfl_down_sync(0xffffffffu, dr, o);
    }
    int lane = j & 31, hd = j >> 5;
    if (lane == 0){ g_cl[hd]=cl; g_dl[hd]=dl; g_cr[hd]=cr; g_dr[hd]=dr; }
}

__global__ void k_l0_eler(const float* __restrict__ weights){
    int tid = blockIdx.x*blockDim.x + threadIdx.x;
    if (tid >= NB4) return;
    int n = tid >> 2, h = tid & 3;
    float w = weights[n];
    g_el[tid] = w*g_cl[h] + g_dl[h];
    g_er[tid] = w*g_cr[h] + g_dr[h];
}

// ---------------- register-blocked GEMM (layers 1,2) -----------------------
// g_h = leaky(g_x) @ W^T ;  BM=BN=128, BK=8, 256 thr, 8x8/thread via f32x2
#define BM 128
#define BN 128
#define BK 8
#define LDP (BM+4)
__global__ void __launch_bounds__(256, 2)
k_gemm(const float* __restrict__ W){
    __shared__ __align__(16) float As[BK][LDP];
    __shared__ __align__(16) float Bs[BK][LDP];
    int t    = threadIdx.x;
    int row0 = blockIdx.x * BM;
    int tx = t & 15, ty = t >> 4;             // 16 x 16 thread grid
    int lr = t >> 1;                          // 0..127
    int lc = (t & 1) * 4;                     // 0 or 4

    ull acc[8][4];
    ull z = pk2(0.f, 0.f);
    #pragma unroll
    for (int i = 0; i < 8; i++)
        #pragma unroll
        for (int j = 0; j < 4; j++) acc[i][j] = z;

    for (int k0 = 0; k0 < DD; k0 += BK){
        float4 xa = *(const float4*)&g_x[(size_t)(row0 + lr)*DD + k0 + lc];
        xa.x = (xa.x >= 0.f) ? xa.x : 0.01f*xa.x;
        xa.y = (xa.y >= 0.f) ? xa.y : 0.01f*xa.y;
        xa.z = (xa.z >= 0.f) ? xa.z : 0.01f*xa.z;
        xa.w = (xa.w >= 0.f) ? xa.w : 0.01f*xa.w;
        float4 wb = *(const float4*)&W[lr*DD + k0 + lc];
        As[lc+0][lr] = xa.x; As[lc+1][lr] = xa.y;
        As[lc+2][lr] = xa.z; As[lc+3][lr] = xa.w;
        Bs[lc+0][lr] = wb.x; Bs[lc+1][lr] = wb.y;
        Bs[lc+2][lr] = wb.z; Bs[lc+3][lr] = wb.w;
        __syncthreads();

        #pragma unroll
        for (int kk = 0; kk < BK; kk++){
            float a[8];
            *(float4*)&a[0] = *(const float4*)&As[kk][ty*8];
            *(float4*)&a[4] = *(const float4*)&As[kk][ty*8+4];
            float4 b0 = *(const float4*)&Bs[kk][tx*8];
            float4 b1 = *(const float4*)&Bs[kk][tx*8+4];
            ull b2[4];
            b2[0] = pk2(b0.x, b0.y); b2[1] = pk2(b0.z, b0.w);
            b2[2] = pk2(b1.x, b1.y); b2[3] = pk2(b1.z, b1.w);
            #pragma unroll
            for (int i = 0; i < 8; i++){
                ull ai = pk2(a[i], a[i]);
                #pragma unroll
                for (int j = 0; j < 4; j++)
                    acc[i][j] = ffma2(ai, b2[j], acc[i][j]);
            }
        }
        __syncthreads();
    }

    #pragma unroll
    for (int i = 0; i < 8; i++){
        float o[8];
        upk2(acc[i][0], o[0], o[1]); upk2(acc[i][1], o[2], o[3]);
        upk2(acc[i][2], o[4], o[5]); upk2(acc[i][3], o[6], o[7]);
        float* dstp = &g_h[(size_t)(row0 + ty*8 + i)*DD + tx*8];
        *(float4*)dstp       = *(float4*)&o[0];
        *(float4*)(dstp + 4) = *(float4*)&o[4];
    }
}

// ---------------- el/er from g_h (coalesced, warp per node) -----------------
__global__ void k_eler(const float* __restrict__ al, const float* __restrict__ ar){
    int wid = (blockIdx.x*blockDim.x + threadIdx.x) >> 5;
    if (wid >= NN) return;
    int lane = threadIdx.x & 31;
    float4 hv  = *(const float4*)&g_h[(size_t)wid*DD + lane*4];
    float4 alv = *(const float4*)&al[lane*4];
    float4 arv = *(const float4*)&ar[lane*4];
    float sl = hv.x*alv.x + hv.y*alv.y + hv.z*alv.z + hv.w*alv.w;
    float sr = hv.x*arv.x + hv.y*arv.y + hv.z*arv.z + hv.w*arv.w;
    #pragma unroll
    for (int o = 4; o; o >>= 1){
        sl += __shfl_down_sync(0xffffffffu, sl, o);
        sr += __shfl_down_sync(0xffffffffu, sr, o);
    }
    if ((lane & 7) == 0){
        int h = lane >> 3;
        g_el[wid*4 + h] = sl;
        g_er[wid*4 + h] = sr;
    }
}

// ---------------- edge softmax (per node,head; serial over in-edges) -------
__global__ void k_softmax(){
    int tid = blockIdx.x*blockDim.x + threadIdx.x;
    if (tid >= NB4) return;
    int n = tid >> 2, h = tid & 3;
    float ern = g_er[tid];
    int start = g_off[n], end = start + g_deg[n];
    float mx = -3.0e38f;
    for (int p = start; p < end; p++){
        float e = g_el[g_csrc[p]*4 + h] + ern;
        e = (e >= 0.f) ? e : 0.2f*e;
        g_e[p*4 + h] = e;
        mx = fmaxf(mx, e);
    }
    float sum = 0.f;
    for (int p = start; p < end; p++){
        float a = __expf(g_e[p*4 + h] - mx);
        g_e[p*4 + h] = a;
        sum += a;
    }
    g_invs[tid] = 1.0f / sum;
}

// ---------------- aggregation: warp per dst node (g_h -> g_x) ---------------
__global__ void k_aggr(const float* __restrict__ bias){
    int wid = (blockIdx.x*blockDim.x + threadIdx.x) >> 5;
    if (wid >= NN) return;
    int lane = threadIdx.x & 31;
    int head = lane >> 3;
    float invs = g_invs[wid*4 + head];
    float4 acc = *(const float4*)&bias[lane*4];
    int start = g_off[wid], end = start + g_deg[wid];
    for (int p = start; p < end; p++){
        int s = g_csrc[p];
        float w = g_e[p*4 + head] * invs;
        float4 hv = *(const float4*)&g_h[(size_t)s*DD + lane*4];
        acc.x += hv.x*w; acc.y += hv.y*w; acc.z += hv.z*w; acc.w += hv.w*w;
    }
    *(float4*)&g_x[(size_t)wid*DD + lane*4] = acc;
}

// layer-0 variant: h0[src] = weights[src]*c + d  (4B gather), writes g_x
__global__ void k_aggr0(const float* __restrict__ weights,
                        const float* __restrict__ bias){
    int wid = (blockIdx.x*blockDim.x + threadIdx.x) >> 5;
    if (wid >= NN) return;
    int lane = threadIdx.x & 31;
    int head = lane >> 3;
    float invs = g_invs[wid*4 + head];
    float4 c4 = *(const float4*)&g_c[lane*4];
    float4 d4 = *(const float4*)&g_d[lane*4];
    float4 acc = *(const float4*)&bias[lane*4];
    int start = g_off[wid], end = start + g_deg[wid];
    for (int p = start; p < end; p++){
        int s = g_csrc[p];
        float ws = weights[s];
        float w = g_e[p*4 + head] * invs;
        acc.x += (ws*c4.x + d4.x)*w;
        acc.y += (ws*c4.y + d4.y)*w;
        acc.z += (ws*c4.z + d4.z)*w;
        acc.w += (ws*c4.w + d4.w)*w;
    }
    *(float4*)&g_x[(size_t)wid*DD + lane*4] = acc;
}

// layer-2 aggregation fused with prediction head: out[n] = dot(agg, pW) + pb
__global__ void k_aggr_pred(const float* __restrict__ bias,
                            const float* __restrict__ pw,
                            const float* __restrict__ pb,
                            float* __restrict__ out){
    int wid = (blockIdx.x*blockDim.x + threadIdx.x) >> 5;
    if (wid >= NN) return;
    int lane = threadIdx.x & 31;
    int head = lane >> 3;
    float invs = g_invs[wid*4 + head];
    float4 acc = *(const float4*)&bias[lane*4];
    int start = g_off[wid], end = start + g_deg[wid];
    for (int p = start; p < end; p++){
        int s = g_csrc[p];
        float w = g_e[p*4 + head] * invs;
        float4 hv = *(const float4*)&g_h[(size_t)s*DD + lane*4];
        acc.x += hv.x*w; acc.y += hv.y*w; acc.z += hv.z*w; acc.w += hv.w*w;
    }
    float4 wv = *(const float4*)&pw[lane*4];
    float s = acc.x*wv.x + acc.y*wv.y + acc.z*wv.z + acc.w*wv.w;
    #pragma unroll
    for (int o = 16; o; o >>= 1) s += __shfl_down_sync(0xffffffffu, s, o);
    if (lane == 0) out[wid] = s + pb[0];
}

// ---------------- launch ----------------------------------------------------
// NOTE: never pass __device__ symbols as kernel arguments from host code —
// on GB300 (ATS) that silently binds the HOST shadow variable.
extern "C" void kernel_launch(void* const* d_in, const int* in_sizes, int n_in,
                              void* d_out, int out_size){
    const float* weights = (const float*)d_in[0];
    const float* lin_W   = (const float*)d_in[1];
    const float* lin_b   = (const float*)d_in[2];
    const float* fc_W    = (const float*)d_in[3];
    const float* attn_l  = (const float*)d_in[4];
    const float* attn_r  = (const float*)d_in[5];
    const float* conv_b  = (const float*)d_in[6];
    const float* pred_W  = (const float*)d_in[7];
    const float* pred_b  = (const float*)d_in[8];
    const int*   src     = (const int*)d_in[9];
    const int*   dst     = (const int*)d_in[10];
    float* out = (float*)d_out;

    // --- CSR build (once per launch) ---
    k_init_deg<<<(NN+255)/256, 256>>>();
    k_hist<<<(EE+255)/256, 256>>>(dst);
    k_scan1<<<98, 1024>>>();
    k_scan2<<<1, 128>>>();
    k_scan3<<<98, 1024>>>();
    k_fill<<<(ETOT+255)/256, 256>>>(src, dst);

    // --- layer 0 (rank-1 features) ---
    k_l0prep<<<1, 128>>>(lin_W, lin_b, fc_W, attn_l, attn_r);
    k_l0_eler<<<(NB4+255)/256, 256>>>(weights);
    k_softmax<<<(NB4+255)/256, 256>>>();
    k_aggr0<<<(NN*32+255)/256, 256>>>(weights, conv_b);

    // --- layer 1 ---
    k_gemm<<<NNP/BM, 256>>>(fc_W + 1*DD*DD);
    k_eler<<<(NN*32+255)/256, 256>>>(attn_l + 1*DD, attn_r + 1*DD);
    k_softmax<<<(NB4+255)/256, 256>>>();
    k_aggr<<<(NN*32+255)/256, 256>>>(conv_b + 1*DD);

    // --- layer 2 ---
    k_gemm<<<NNP/BM, 256>>>(fc_W + 2*DD*DD);
    k_eler<<<(NN*32+255)/256, 256>>>(attn_l + 2*DD, attn_r + 2*DD);
    k_softmax<<<(NB4+255)/256, 256>>>();
    k_aggr_pred<<<(NN*32+255)/256, 256>>>(conv_b + 2*DD, pred_W, pred_b, out);
}

// round 6
// speedup vs baseline: 4.8372x; 1.0282x over previous
#include <cuda_runtime.h>
#include <cuda_bf16.h>

#define NN   100000
#define NNP  100096          // 782 * 128 (row-padded for GEMM tiles)
#define EE   600000
#define ETOT 700000          // EE + NN self loops
#define DD   128
#define HH   4
#define FF   32
#define NB4  (NN*4)

typedef unsigned long long ull;

// ---------------- scratch: device symbols, used ONLY inside device code ----
__device__ __align__(256) float g_x[NNP*DD];   // current node features
__device__ __align__(256) float g_h[NNP*DD];   // fc output of current layer
__device__ __align__(256) float g_el[NB4];
__device__ __align__(256) float g_er[NB4];
__device__ __align__(256) int   g_deg[NN];
__device__ __align__(256) int   g_off[NN];
__device__ __align__(256) int   g_cur[NN];
__device__ __align__(256) int   g_bsum[128];
__device__ __align__(256) int   g_csrc[ETOT];
__device__ __align__(256) float g_c[DD];
__device__ __align__(256) float g_d[DD];
__device__ float g_cl[HH], g_dl[HH], g_cr[HH], g_dr[HH];

// ---------------- f32x2 packed helpers ------------------------------------
__device__ __forceinline__ ull pk2(float x, float y){
    ull r; asm("mov.b64 %0, {%1, %2};" : "=l"(r) : "f"(x), "f"(y)); return r;
}
__device__ __forceinline__ void upk2(ull v, float& x, float& y){
    asm("mov.b64 {%0, %1}, %2;" : "=f"(x), "=f"(y) : "l"(v));
}
__device__ __forceinline__ ull ffma2(ull a, ull b, ull c){
    ull d; asm("fma.rn.f32x2 %0, %1, %2, %3;" : "=l"(d) : "l"(a), "l"(b), "l"(c)); return d;
}
__device__ __forceinline__ float lrelu02(float x){ return (x >= 0.f) ? x : 0.2f*x; }

// ---------------- CSR build ------------------------------------------------
__global__ void k_init_deg(){
    int i = blockIdx.x*blockDim.x + threadIdx.x;
    if (i < NN) g_deg[i] = 1;                 // self loop
}

__global__ void k_hist(const int* __restrict__ dst){
    int i = blockIdx.x*blockDim.x + threadIdx.x;
    if (i < EE) atomicAdd(&g_deg[dst[i]], 1);
}

__global__ void k_scan1(){                    // per-1024-block sums of deg
    int i = blockIdx.x*1024 + threadIdx.x;
    int v = (i < NN) ? g_deg[i] : 0;
    __shared__ int sh[32];
    int lane = threadIdx.x & 31, wd = threadIdx.x >> 5;
    #pragma unroll
    for (int o = 16; o; o >>= 1) v += __shfl_down_sync(0xffffffffu, v, o);
    if (lane == 0) sh[wd] = v;
    __syncthreads();
    if (wd == 0){
        int s = sh[lane];
        #pragma unroll
        for (int o = 16; o; o >>= 1) s += __shfl_down_sync(0xffffffffu, s, o);
        if (lane == 0) g_bsum[blockIdx.x] = s;
    }
}

__global__ void k_scan2(){                    // exclusive scan of 98 block sums
    const int NBK = 98;
    int t = threadIdx.x;                      // 128 threads
    int v = (t < NBK) ? g_bsum[t] : 0;
    int orig = v;
    int lane = t & 31, wd = t >> 5;
    #pragma unroll
    for (int o = 1; o < 32; o <<= 1){
        int u = __shfl_up_sync(0xffffffffu, v, o);
        if (lane >= o) v += u;
    }
    __shared__ int sh[4];
    if (lane == 31) sh[wd] = v;
    __syncthreads();
    int add = 0;
    for (int w = 0; w < wd; w++) add += sh[w];
    if (t < NBK) g_bsum[t] = v - orig + add;
}

__global__ void k_scan3(){                    // per-block exclusive scan + base
    int i = blockIdx.x*1024 + threadIdx.x;
    int v = (i < NN) ? g_deg[i] : 0;
    int orig = v;
    int lane = threadIdx.x & 31, wd = threadIdx.x >> 5;
    #pragma unroll
    for (int o = 1; o < 32; o <<= 1){
        int u = __shfl_up_sync(0xffffffffu, v, o);
        if (lane >= o) v += u;
    }
    __shared__ int sh[32];
    if (lane == 31) sh[wd] = v;
    __syncthreads();
    if (wd == 0){
        int s = sh[lane];
        #pragma unroll
        for (int o = 1; o < 32; o <<= 1){
            int u = __shfl_up_sync(0xffffffffu, s, o);
            if (lane >= o) s += u;
        }
        sh[lane] = s;
    }
    __syncthreads();
    int add = ((wd > 0) ? sh[wd-1] : 0) + g_bsum[blockIdx.x];
    int excl = v - orig + add;
    if (i < NN){ g_off[i] = excl; g_cur[i] = excl; }
}

__global__ void k_fill(const int* __restrict__ src, const int* __restrict__ dst){
    int i = blockIdx.x*blockDim.x + threadIdx.x;
    if (i < EE){
        int d = dst[i];
        int pos = atomicAdd(&g_cur[d], 1);
        g_csrc[pos] = src[i];
    } else if (i < ETOT){
        int n = i - EE;
        int pos = atomicAdd(&g_cur[n], 1);
        g_csrc[pos] = n;
    }
}

// ---------------- layer 0 (rank-1) ----------------------------------------
__global__ void k_l0prep(const float* __restrict__ linW, const float* __restrict__ linb,
                         const float* __restrict__ W0,
                         const float* __restrict__ al0, const float* __restrict__ ar0){
    int j = threadIdx.x;                      // 128 threads, 1 block
    float c = 0.f, d = 0.f;
    const float* wr = W0 + j*DD;
    #pragma unroll 8
    for (int k = 0; k < DD; k++){
        float w = wr[k];
        c += linW[k]*w;
        d += linb[k]*w;
    }
    g_c[j] = c; g_d[j] = d;
    float alv = al0[j], arv = ar0[j];
    float cl = c*alv, dl = d*alv, cr = c*arv, dr = d*arv;
    #pragma unroll
    for (int o = 16; o; o >>= 1){
        cl += __shfl_down_sync(0xffffffffu, cl, o);
        dl += __shfl_down_sync(0xffffffffu, dl, o);
        cr += __shfl_down_sync(0xffffffffu, cr, o);
        dr += __shfl_down_sync(0xffffffffu, dr, o);
    }
    int lane = j & 31, hd = j >> 5;
    if (lane == 0){ g_cl[hd]=cl; g_dl[hd]=dl; g_cr[hd]=cr; g_dr[hd]=dr; }
}

__global__ void k_l0_eler(const float* __restrict__ weights){
    int tid = blockIdx.x*blockDim.x + threadIdx.x;
    if (tid >= NB4) return;
    int n = tid >> 2, h = tid & 3;
    float w = weights[n];
    g_el[tid] = w*g_cl[h] + g_dl[h];
    g_er[tid] = w*g_cr[h] + g_dr[h];
}

// ---------------- register-blocked GEMM + fused el/er (layers 1,2) ---------
// g_h = leaky(g_x) @ W^T ; el/er computed from the register tile in epilogue
#define BM 128
#define BK 8
#define LDP (BM+4)
__global__ void __launch_bounds__(256, 2)
k_gemm(const float* __restrict__ W,
       const float* __restrict__ al, const float* __restrict__ ar){
    __shared__ __align__(16) float As[BK][LDP];
    __shared__ __align__(16) float Bs[BK][LDP];
    int t    = threadIdx.x;
    int row0 = blockIdx.x * BM;
    int tx = t & 15, ty = t >> 4;             // 16 x 16 thread grid
    int lr = t >> 1;                          // 0..127
    int lc = (t & 1) * 4;                     // 0 or 4

    ull acc[8][4];
    ull z = pk2(0.f, 0.f);
    #pragma unroll
    for (int i = 0; i < 8; i++)
        #pragma unroll
        for (int j = 0; j < 4; j++) acc[i][j] = z;

    for (int k0 = 0; k0 < DD; k0 += BK){
        float4 xa = *(const float4*)&g_x[(size_t)(row0 + lr)*DD + k0 + lc];
        xa.x = (xa.x >= 0.f) ? xa.x : 0.01f*xa.x;
        xa.y = (xa.y >= 0.f) ? xa.y : 0.01f*xa.y;
        xa.z = (xa.z >= 0.f) ? xa.z : 0.01f*xa.z;
        xa.w = (xa.w >= 0.f) ? xa.w : 0.01f*xa.w;
        float4 wb = *(const float4*)&W[lr*DD + k0 + lc];
        As[lc+0][lr] = xa.x; As[lc+1][lr] = xa.y;
        As[lc+2][lr] = xa.z; As[lc+3][lr] = xa.w;
        Bs[lc+0][lr] = wb.x; Bs[lc+1][lr] = wb.y;
        Bs[lc+2][lr] = wb.z; Bs[lc+3][lr] = wb.w;
        __syncthreads();

        #pragma unroll
        for (int kk = 0; kk < BK; kk++){
            float a[8];
            *(float4*)&a[0] = *(const float4*)&As[kk][ty*8];
            *(float4*)&a[4] = *(const float4*)&As[kk][ty*8+4];
            float4 b0 = *(const float4*)&Bs[kk][tx*8];
            float4 b1 = *(const float4*)&Bs[kk][tx*8+4];
            ull b2[4];
            b2[0] = pk2(b0.x, b0.y); b2[1] = pk2(b0.z, b0.w);
            b2[2] = pk2(b1.x, b1.y); b2[3] = pk2(b1.z, b1.w);
            #pragma unroll
            for (int i = 0; i < 8; i++){
                ull ai = pk2(a[i], a[i]);
                #pragma unroll
                for (int j = 0; j < 4; j++)
                    acc[i][j] = ffma2(ai, b2[j], acc[i][j]);
            }
        }
        __syncthreads();
    }

    // epilogue: store h, compute el/er (all 8 cols of this thread sit in head tx>>2)
    float al_v[8], ar_v[8];
    #pragma unroll
    for (int j = 0; j < 8; j++){ al_v[j] = al[tx*8+j]; ar_v[j] = ar[tx*8+j]; }
    int hd = tx >> 2;
    #pragma unroll
    for (int i = 0; i < 8; i++){
        float o[8];
        upk2(acc[i][0], o[0], o[1]); upk2(acc[i][1], o[2], o[3]);
        upk2(acc[i][2], o[4], o[5]); upk2(acc[i][3], o[6], o[7]);
        int row = row0 + ty*8 + i;
        float* dstp = &g_h[(size_t)row*DD + tx*8];
        *(float4*)dstp       = *(float4*)&o[0];
        *(float4*)(dstp + 4) = *(float4*)&o[4];
        float sl = 0.f, sr = 0.f;
        #pragma unroll
        for (int j = 0; j < 8; j++){ sl += o[j]*al_v[j]; sr += o[j]*ar_v[j]; }
        sl += __shfl_xor_sync(0xffffffffu, sl, 1);
        sl += __shfl_xor_sync(0xffffffffu, sl, 2);
        sr += __shfl_xor_sync(0xffffffffu, sr, 1);
        sr += __shfl_xor_sync(0xffffffffu, sr, 2);
        if ((tx & 3) == 0 && row < NN){
            g_el[row*4 + hd] = sl;
            g_er[row*4 + hd] = sr;
        }
    }
}

// ---------------- fused edge-softmax + aggregation (warp per node) ---------
// phase 1: lanes over (edge,head); per-head max via shfl
// phase 2: exp + sum in regs; alpha & csrc staged in shared (deg<=32 fast path)
// phase 3: lanes over features; aggregate; MODE: 0 = g_h gather, 1 = layer-0
//          rank-1, 2 = g_h gather + fused prediction head
template<int MODE>
__device__ __forceinline__ void smax_aggr_body(
    const float* __restrict__ bias, const float* __restrict__ weights,
    const float* __restrict__ pw, const float* __restrict__ pb,
    float* __restrict__ out)
{
    int wid = (blockIdx.x*blockDim.x + threadIdx.x) >> 5;
    if (wid >= NN) return;
    int lane = threadIdx.x & 31;
    int wd   = (threadIdx.x >> 5) & 7;
    __shared__ float sAlpha[8][128];
    __shared__ int   sSrc[8][32];

    int start = g_off[wid];
    int deg   = g_deg[wid];

    // ---- phase 1: e + max ----
    int eh_e = lane >> 2;                    // edge slot within chunk (0..7)
    int eh_h = lane & 3;                     // head
    float er_h = g_er[wid*4 + eh_h];
    float ev[4];
    float mx = -3.0e38f;
    #pragma unroll
    for (int c = 0; c < 4; c++){
        int pi = c*8 + eh_e;
        float e = -3.0e38f;
        if (pi < deg){
            int s = g_csrc[start + pi];
            if (eh_h == 0) sSrc[wd][pi] = s;
            e = lrelu02(g_el[s*4 + eh_h] + er_h);
        }
        ev[c] = e;
        mx = fmaxf(mx, e);
    }
    for (int pi = 32 + eh_e; pi < deg; pi += 8){          // rare overflow
        int s = g_csrc[start + pi];
        mx = fmaxf(mx, lrelu02(g_el[s*4 + eh_h] + er_h));
    }
    mx = fmaxf(mx, __shfl_xor_sync(0xffffffffu, mx, 4));
    mx = fmaxf(mx, __shfl_xor_sync(0xffffffffu, mx, 8));
    mx = fmaxf(mx, __shfl_xor_sync(0xffffffffu, mx, 16));

    // ---- phase 2: exp + sum ----
    float sum = 0.f;
    #pragma unroll
    for (int c = 0; c < 4; c++){
        int pi = c*8 + eh_e;
        float a = 0.f;
        if (pi < deg) a = __expf(ev[c] - mx);
        ev[c] = a;
        sum += a;
    }
    for (int pi = 32 + eh_e; pi < deg; pi += 8){          // rare overflow
        int s = g_csrc[start + pi];
        sum += __expf(lrelu02(g_el[s*4 + eh_h] + er_h) - mx);
    }
    sum += __shfl_xor_sync(0xffffffffu, sum, 4);
    sum += __shfl_xor_sync(0xffffffffu, sum, 8);
    sum += __shfl_xor_sync(0xffffffffu, sum, 16);
    float invs = 1.0f / sum;

    #pragma unroll
    for (int c = 0; c < 4; c++){
        int pi = c*8 + eh_e;
        if (pi < deg) sAlpha[wd][pi*4 + eh_h] = ev[c]*invs;
    }
    __syncwarp();

    // ---- phase 3: aggregate over features ----
    int head = lane >> 3;
    float invs_h = __shfl_sync(0xffffffffu, invs, head);
    float mx_h   = __shfl_sync(0xffffffffu, mx,   head);
    float er_hh  = __shfl_sync(0xffffffffu, er_h, head);

    float4 acc = *(const float4*)&bias[lane*4];
    float4 c4, d4;
    if (MODE == 1){
        c4 = *(const float4*)&g_c[lane*4];
        d4 = *(const float4*)&g_d[lane*4];
    }
    int lim = deg < 32 ? deg : 32;
    for (int p = 0; p < lim; p++){
        int s   = sSrc[wd][p];
        float w = sAlpha[wd][p*4 + head];
        if (MODE == 1){
            float ws = weights[s];
            acc.x += (ws*c4.x + d4.x)*w;
            acc.y += (ws*c4.y + d4.y)*w;
            acc.z += (ws*c4.z + d4.z)*w;
            acc.w += (ws*c4.w + d4.w)*w;
        } else {
            float4 hv = *(const float4*)&g_h[(size_t)s*DD + lane*4];
            acc.x += hv.x*w; acc.y += hv.y*w; acc.z += hv.z*w; acc.w += hv.w*w;
        }
    }
    for (int p = 32; p < deg; p++){                       // rare overflow
        int s = g_csrc[start + p];
        float w = __expf(lrelu02(g_el[s*4 + head] + er_hh) - mx_h) * invs_h;
        if (MODE == 1){
            float ws = weights[s];
            acc.x += (ws*c4.x + d4.x)*w;
            acc.y += (ws*c4.y + d4.y)*w;
            acc.z += (ws*c4.z + d4.z)*w;
            acc.w += (ws*c4.w + d4.w)*w;
        } else {
            float4 hv = *(const float4*)&g_h[(size_t)s*DD + lane*4];
            acc.x += hv.x*w; acc.y += hv.y*w; acc.z += hv.z*w; acc.w += hv.w*w;
        }
    }

    if (MODE == 2){
        float4 wv = *(const float4*)&pw[lane*4];
        float sdot = acc.x*wv.x + acc.y*wv.y + acc.z*wv.z + acc.w*wv.w;
        #pragma unroll
        for (int o = 16; o; o >>= 1) sdot += __shfl_down_sync(0xffffffffu, sdot, o);
        if (lane == 0) out[wid] = sdot + pb[0];
    } else {
        *(float4*)&g_x[(size_t)wid*DD + lane*4] = acc;
    }
}

__global__ void k_smax_aggr(const float* __restrict__ bias){
    smax_aggr_body<0>(bias, nullptr, nullptr, nullptr, nullptr);
}
__global__ void k_smax_aggr0(const float* __restrict__ weights,
                             const float* __restrict__ bias){
    smax_aggr_body<1>(bias, weights, nullptr, nullptr, nullptr);
}
__global__ void k_smax_aggr_pred(const float* __restrict__ bias,
                                 const float* __restrict__ pw,
                                 const float* __restrict__ pb,
                                 float* __restrict__ out){
    smax_aggr_body<2>(bias, nullptr, pw, pb, out);
}

// ---------------- launch ----------------------------------------------------
// NOTE: never pass __device__ symbols as kernel arguments from host code —
// on GB300 (ATS) that silently binds the HOST shadow variable.
extern "C" void kernel_launch(void* const* d_in, const int* in_sizes, int n_in,
                              void* d_out, int out_size){
    const float* weights = (const float*)d_in[0];
    const float* lin_W   = (const float*)d_in[1];
    const float* lin_b   = (const float*)d_in[2];
    const float* fc_W    = (const float*)d_in[3];
    const float* attn_l  = (const float*)d_in[4];
    const float* attn_r  = (const float*)d_in[5];
    const float* conv_b  = (const float*)d_in[6];
    const float* pred_W  = (const float*)d_in[7];
    const float* pred_b  = (const float*)d_in[8];
    const int*   src     = (const int*)d_in[9];
    const int*   dst     = (const int*)d_in[10];
    float* out = (float*)d_out;

    // --- CSR build (once per launch) ---
    k_init_deg<<<(NN+255)/256, 256>>>();
    k_hist<<<(EE+255)/256, 256>>>(dst);
    k_scan1<<<98, 1024>>>();
    k_scan2<<<1, 128>>>();
    k_scan3<<<98, 1024>>>();
    k_fill<<<(ETOT+255)/256, 256>>>(src, dst);

    // --- layer 0 (rank-1 features) ---
    k_l0prep<<<1, 128>>>(lin_W, lin_b, fc_W, attn_l, attn_r);
    k_l0_eler<<<(NB4+255)/256, 256>>>(weights);
    k_smax_aggr0<<<(NN*32+255)/256, 256>>>(weights, conv_b);

    // --- layer 1 (GEMM fuses el/er epilogue) ---
    k_gemm<<<NNP/BM, 256>>>(fc_W + 1*DD*DD, attn_l + 1*DD, attn_r + 1*DD);
    k_smax_aggr<<<(NN*32+255)/256, 256>>>(conv_b + 1*DD);

    // --- layer 2 ---
    k_gemm<<<NNP/BM, 256>>>(fc_W + 2*DD*DD, attn_l + 2*DD, attn_r + 2*DD);
    k_smax_aggr_pred<<<(NN*32+255)/256, 256>>>(conv_b + 2*DD, pred_W, pred_b, out);
}

// round 8
// speedup vs baseline: 5.8368x; 1.2067x over previous
#include <cuda_runtime.h>
#include <cuda_bf16.h>
#include <cstdint>

#define NN   100000
#define NNP  100096          // 782 * 128 (row-padded for GEMM tiles)
#define EE   600000
#define ETOT 700000          // EE + NN self loops
#define DD   128
#define HH   4
#define FF   32
#define NB4  (NN*4)

typedef unsigned long long ull;

// ---------------- scratch: device symbols, used ONLY inside device code ----
__device__ __align__(256) float g_x[NNP*DD];   // current node features
__device__ __align__(256) float g_h[NNP*DD];   // fc output of current layer
__device__ __align__(256) float g_el[NB4];
__device__ __align__(256) float g_er[NB4];
__device__ __align__(256) int   g_deg[NN];
__device__ __align__(256) int   g_off[NN];
__device__ __align__(256) int   g_cur[NN];
__device__ __align__(256) int   g_bsum[128];
__device__ __align__(256) int   g_csrc[ETOT];
__device__ __align__(256) float g_c[DD];
__device__ __align__(256) float g_d[DD];
__device__ float g_cl[HH], g_dl[HH], g_cr[HH], g_dr[HH];

__device__ __forceinline__ float lrelu02(float x){ return (x >= 0.f) ? x : 0.2f*x; }

// bf16 hi/lo split of two floats -> packed bf16x2 words
__device__ __forceinline__ uint32_t bfsplit2(float x0, float x1, uint32_t& lo){
    __nv_bfloat16 h0 = __float2bfloat16(x0);
    __nv_bfloat16 h1 = __float2bfloat16(x1);
    float r0 = x0 - __bfloat162float(h0);
    float r1 = x1 - __bfloat162float(h1);
    __nv_bfloat16 g0 = __float2bfloat16(r0);
    __nv_bfloat16 g1 = __float2bfloat16(r1);
    lo = (uint32_t)__bfloat16_as_ushort(g0) | ((uint32_t)__bfloat16_as_ushort(g1) << 16);
    return (uint32_t)__bfloat16_as_ushort(h0) | ((uint32_t)__bfloat16_as_ushort(h1) << 16);
}

// warp-level bf16 MMA (baseline sm_80+ PTX; compiles at compute_103)
#define MMA_BF16(d, a, b0, b1) \
    asm volatile("mma.sync.aligned.m16n8k16.row.col.f32.bf16.bf16.f32 " \
        "{%0,%1,%2,%3}, {%4,%5,%6,%7}, {%8,%9}, {%0,%1,%2,%3};" \
        : "+f"((d)[0]), "+f"((d)[1]), "+f"((d)[2]), "+f"((d)[3]) \
        : "r"((a)[0]), "r"((a)[1]), "r"((a)[2]), "r"((a)[3]), "r"(b0), "r"(b1))

// ---------------- CSR build ------------------------------------------------
__global__ void k_init_deg(){
    int i = blockIdx.x*blockDim.x + threadIdx.x;
    if (i < NN) g_deg[i] = 1;                 // self loop
}

__global__ void k_hist(const int* __restrict__ dst){
    int i = blockIdx.x*blockDim.x + threadIdx.x;
    if (i < EE) atomicAdd(&g_deg[dst[i]], 1);
}

__global__ void k_scan1(){                    // per-1024-block sums of deg
    int i = blockIdx.x*1024 + threadIdx.x;
    int v = (i < NN) ? g_deg[i] : 0;
    __shared__ int sh[32];
    int lane = threadIdx.x & 31, wd = threadIdx.x >> 5;
    #pragma unroll
    for (int o = 16; o; o >>= 1) v += __shfl_down_sync(0xffffffffu, v, o);
    if (lane == 0) sh[wd] = v;
    __syncthreads();
    if (wd == 0){
        int s = sh[lane];
        #pragma unroll
        for (int o = 16; o; o >>= 1) s += __shfl_down_sync(0xffffffffu, s, o);
        if (lane == 0) g_bsum[blockIdx.x] = s;
    }
}

__global__ void k_scan2(){                    // exclusive scan of 98 block sums
    const int NBK = 98;
    int t = threadIdx.x;                      // 128 threads
    int v = (t < NBK) ? g_bsum[t] : 0;
    int orig = v;
    int lane = t & 31, wd = t >> 5;
    #pragma unroll
    for (int o = 1; o < 32; o <<= 1){
        int u = __shfl_up_sync(0xffffffffu, v, o);
        if (lane >= o) v += u;
    }
    __shared__ int sh[4];
    if (lane == 31) sh[wd] = v;
    __syncthreads();
    int add = 0;
    for (int w = 0; w < wd; w++) add += sh[w];
    if (t < NBK) g_bsum[t] = v - orig + add;
}

__global__ void k_scan3(){                    // per-block exclusive scan + base
    int i = blockIdx.x*1024 + threadIdx.x;
    int v = (i < NN) ? g_deg[i] : 0;
    int orig = v;
    int lane = threadIdx.x & 31, wd = threadIdx.x >> 5;
    #pragma unroll
    for (int o = 1; o < 32; o <<= 1){
        int u = __shfl_up_sync(0xffffffffu, v, o);
        if (lane >= o) v += u;
    }
    __shared__ int sh[32];
    if (lane == 31) sh[wd] = v;
    __syncthreads();
    if (wd == 0){
        int s = sh[lane];
        #pragma unroll
        for (int o = 1; o < 32; o <<= 1){
            int u = __shfl_up_sync(0xffffffffu, s, o);
            if (lane >= o) s += u;
        }
        sh[lane] = s;
    }
    __syncthreads();
    int add = ((wd > 0) ? sh[wd-1] : 0) + g_bsum[blockIdx.x];
    int excl = v - orig + add;
    if (i < NN){ g_off[i] = excl; g_cur[i] = excl; }
}

__global__ void k_fill(const int* __restrict__ src, const int* __restrict__ dst){
    int i = blockIdx.x*blockDim.x + threadIdx.x;
    if (i < EE){
        int d = dst[i];
        int pos = atomicAdd(&g_cur[d], 1);
        g_csrc[pos] = src[i];
    } else if (i < ETOT){
        int n = i - EE;
        int pos = atomicAdd(&g_cur[n], 1);
        g_csrc[pos] = n;
    }
}

// ---------------- layer 0 (rank-1) ----------------------------------------
__global__ void k_l0prep(const float* __restrict__ linW, const float* __restrict__ linb,
                         const float* __restrict__ W0,
                         const float* __restrict__ al0, const float* __restrict__ ar0){
    int j = threadIdx.x;                      // 128 threads, 1 block
    float c = 0.f, d = 0.f;
    const float* wr = W0 + j*DD;
    #pragma unroll 8
    for (int k = 0; k < DD; k++){
        float w = wr[k];
        c += linW[k]*w;
        d += linb[k]*w;
    }
    g_c[j] = c; g_d[j] = d;
    float alv = al0[j], arv = ar0[j];
    float cl = c*alv, dl = d*alv, cr = c*arv, dr = d*arv;
    #pragma unroll
    for (int o = 16; o; o >>= 1){
        cl += __shfl_down_sync(0xffffffffu, cl, o);
        dl += __shfl_down_sync(0xffffffffu, dl, o);
        cr += __shfl_down_sync(0xffffffffu, cr, o);
        dr += __shfl_down_sync(0xffffffffu, dr, o);
    }
    int lane = j & 31, hd = j >> 5;
    if (lane == 0){ g_cl[hd]=cl; g_dl[hd]=dl; g_cr[hd]=cr; g_dr[hd]=dr; }
}

__global__ void k_l0_eler(const float* __restrict__ weights){
    int tid = blockIdx.x*blockDim.x + threadIdx.x;
    if (tid >= NB4) return;
    int n = tid >> 2, h = tid & 3;
    float w = weights[n];
    g_el[tid] = w*g_cl[h] + g_dl[h];
    g_er[tid] = w*g_cr[h] + g_dr[h];
}

// ---------------- HMMA split-bf16 GEMM + fused el/er (layers 1,2) ----------
// g_h = leaky(g_x) @ W^T ; h = Ahi*Whi + Ahi*Wlo + Alo*Whi (fp32 accum)
// smem words (u32): Whi[0], Wlo[8704], xhi[17408], xlo[26112]; pitch 68 w/row
// stage (f32, pitch 132) reuses xhi+xlo region after compute.
#define WP 68
#define SM_WORDS (4*128*WP)
#define SM_BYTES (SM_WORDS*4)

__global__ void __launch_bounds__(256)
k_hgemm(const float* __restrict__ W,
        const float* __restrict__ al, const float* __restrict__ ar){
    extern __shared__ __align__(16) uint32_t sm[];
    uint32_t* Whi = sm;
    uint32_t* Wlo = sm + 128*WP;
    uint32_t* Xhi = sm + 2*128*WP;
    uint32_t* Xlo = sm + 3*128*WP;
    float*    stagef = (float*)(sm + 2*128*WP);   // aliases Xhi/Xlo (after sync)

    int tid  = threadIdx.x;
    int w    = tid >> 5;
    int lane = tid & 31;
    int qr   = lane >> 2, qc = lane & 3;
    int row0 = blockIdx.x * 128;
    int rw   = w * 16;

    // ---- convert W and x tiles to split-bf16 smem ----
    {
        const float4* ws = (const float4*)W;
        const float4* xs = (const float4*)&g_x[(size_t)row0*DD];
        #pragma unroll 4
        for (int j = 0; j < 16; j++){
            int idx = j*256 + tid;                 // float4 index (4096 total)
            int r = idx >> 5, c4 = idx & 31;
            float4 v = ws[idx];
            uint32_t lo0, lo1;
            uint32_t hi0 = bfsplit2(v.x, v.y, lo0);
            uint32_t hi1 = bfsplit2(v.z, v.w, lo1);
            Whi[r*WP + c4*2]     = hi0; Whi[r*WP + c4*2 + 1] = hi1;
            Wlo[r*WP + c4*2]     = lo0; Wlo[r*WP + c4*2 + 1] = lo1;
            float4 u = xs[idx];
            u.x = (u.x >= 0.f) ? u.x : 0.01f*u.x;
            u.y = (u.y >= 0.f) ? u.y : 0.01f*u.y;
            u.z = (u.z >= 0.f) ? u.z : 0.01f*u.z;
            u.w = (u.w >= 0.f) ? u.w : 0.01f*u.w;
            uint32_t xh0 = bfsplit2(u.x, u.y, lo0);
            uint32_t xh1 = bfsplit2(u.z, u.w, lo1);
            Xhi[r*WP + c4*2]     = xh0; Xhi[r*WP + c4*2 + 1] = xh1;
            Xlo[r*WP + c4*2]     = lo0; Xlo[r*WP + c4*2 + 1] = lo1;
        }
    }
    __syncthreads();

    // ---- compute: warp w owns rows rw..rw+15, all 128 cols ----
    float acc[16][4];
    #pragma unroll
    for (int nt = 0; nt < 16; nt++)
        #pragma unroll
        for (int i = 0; i < 4; i++) acc[nt][i] = 0.f;

    #pragma unroll
    for (int ks = 0; ks < 8; ks++){
        int abase = (rw + qr)*WP + ks*8 + qc;
        uint32_t ahi[4], alo[4];
        ahi[0] = Xhi[abase];          ahi[1] = Xhi[abase + 8*WP];
        ahi[2] = Xhi[abase + 4];      ahi[3] = Xhi[abase + 8*WP + 4];
        alo[0] = Xlo[abase];          alo[1] = Xlo[abase + 8*WP];
        alo[2] = Xlo[abase + 4];      alo[3] = Xlo[abase + 8*WP + 4];
        #pragma unroll
        for (int nt = 0; nt < 16; nt++){
            int bbase = (nt*8 + qr)*WP + ks*8 + qc;
            uint32_t bh0 = Whi[bbase], bh1 = Whi[bbase + 4];
            uint32_t bl0 = Wlo[bbase], bl1 = Wlo[bbase + 4];
            MMA_BF16(acc[nt], ahi, bh0, bh1);
            MMA_BF16(acc[nt], ahi, bl0, bl1);
            MMA_BF16(acc[nt], alo, bh0, bh1);
        }
    }
    __syncthreads();                              // all warps done reading X smem

    // ---- epilogue: stage h + el/er from fragments ----
    float sl0[4], sr0[4], sl1[4], sr1[4];
    #pragma unroll
    for (int h = 0; h < 4; h++){ sl0[h]=0.f; sr0[h]=0.f; sl1[h]=0.f; sr1[h]=0.f; }
    #pragma unroll
    for (int nt = 0; nt < 16; nt++){
        int col = nt*8 + qc*2;
        float c0 = acc[nt][0], c1 = acc[nt][1], c2 = acc[nt][2], c3 = acc[nt][3];
        *(float2*)&stagef[(rw+qr)*132 + col]   = make_float2(c0, c1);
        *(float2*)&stagef[(rw+qr+8)*132 + col] = make_float2(c2, c3);
        float2 alv = *(const float2*)&al[col];
        float2 arv = *(const float2*)&ar[col];
        int h = nt >> 2;
        sl0[h] += c0*alv.x + c1*alv.y;  sr0[h] += c0*arv.x + c1*arv.y;
        sl1[h] += c2*alv.x + c3*alv.y;  sr1[h] += c2*arv.x + c3*arv.y;
    }
    #pragma unroll
    for (int h = 0; h < 4; h++){
        sl0[h] += __shfl_xor_sync(0xffffffffu, sl0[h], 1);
        sl0[h] += __shfl_xor_sync(0xffffffffu, sl0[h], 2);
        sr0[h] += __shfl_xor_sync(0xffffffffu, sr0[h], 1);
        sr0[h] += __shfl_xor_sync(0xffffffffu, sr0[h], 2);
        sl1[h] += __shfl_xor_sync(0xffffffffu, sl1[h], 1);
        sl1[h] += __shfl_xor_sync(0xffffffffu, sl1[h], 2);
        sr1[h] += __shfl_xor_sync(0xffffffffu, sr1[h], 1);
        sr1[h] += __shfl_xor_sync(0xffffffffu, sr1[h], 2);
    }
    if (qc == 0){
        int r0 = row0 + rw + qr;
        int r1 = r0 + 8;
        if (r0 < NN){
            #pragma unroll
            for (int h = 0; h < 4; h++){ g_el[r0*4+h] = sl0[h]; g_er[r0*4+h] = sr0[h]; }
        }
        if (r1 < NN){
            #pragma unroll
            for (int h = 0; h < 4; h++){ g_el[r1*4+h] = sl1[h]; g_er[r1*4+h] = sr1[h]; }
        }
    }
    __syncthreads();

    // ---- coalesced h writeback ----
    {
        float4* hd = (float4*)&g_h[(size_t)row0*DD];
        #pragma unroll 4
        for (int j = 0; j < 16; j++){
            int idx = j*256 + tid;
            int r = idx >> 5, c4 = idx & 31;
            hd[idx] = *(const float4*)&stagef[r*132 + c4*4];
        }
    }
}

// ---------------- fused edge-softmax + aggregation (warp per node) ---------
template<int MODE>
__device__ __forceinline__ void smax_aggr_body(
    const float* __restrict__ bias, const float* __restrict__ weights,
    const float* __restrict__ pw, const float* __restrict__ pb,
    float* __restrict__ out)
{
    int wid = (blockIdx.x*blockDim.x + threadIdx.x) >> 5;
    if (wid >= NN) return;
    int lane = threadIdx.x & 31;
    int wd   = (threadIdx.x >> 5) & 7;
    __shared__ float sAlpha[8][128];
    __shared__ int   sSrc[8][32];

    int start = g_off[wid];
    int deg   = g_deg[wid];

    // ---- phase 1: e + max ----
    int eh_e = lane >> 2;                    // edge slot within chunk (0..7)
    int eh_h = lane & 3;                     // head
    float er_h = g_er[wid*4 + eh_h];
    float ev[4];
    float mx = -3.0e38f;
    #pragma unroll
    for (int c = 0; c < 4; c++){
        int pi = c*8 + eh_e;
        float e = -3.0e38f;
        if (pi < deg){
            int s = g_csrc[start + pi];
            if (eh_h == 0) sSrc[wd][pi] = s;
            e = lrelu02(g_el[s*4 + eh_h] + er_h);
        }
        ev[c] = e;
        mx = fmaxf(mx, e);
    }
    for (int pi = 32 + eh_e; pi < deg; pi += 8){          // rare overflow
        int s = g_csrc[start + pi];
        mx = fmaxf(mx, lrelu02(g_el[s*4 + eh_h] + er_h));
    }
    mx = fmaxf(mx, __shfl_xor_sync(0xffffffffu, mx, 4));
    mx = fmaxf(mx, __shfl_xor_sync(0xffffffffu, mx, 8));
    mx = fmaxf(mx, __shfl_xor_sync(0xffffffffu, mx, 16));

    // ---- phase 2: exp + sum ----
    float sum = 0.f;
    #pragma unroll
    for (int c = 0; c < 4; c++){
        int pi = c*8 + eh_e;
        float a = 0.f;
        if (pi < deg) a = __expf(ev[c] - mx);
        ev[c] = a;
        sum += a;
    }
    for (int pi = 32 + eh_e; pi < deg; pi += 8){          // rare overflow
        int s = g_csrc[start + pi];
        sum += __expf(lrelu02(g_el[s*4 + eh_h] + er_h) - mx);
    }
    sum += __shfl_xor_sync(0xffffffffu, sum, 4);
    sum += __shfl_xor_sync(0xffffffffu, sum, 8);
    sum += __shfl_xor_sync(0xffffffffu, sum, 16);
    float invs = 1.0f / sum;

    #pragma unroll
    for (int c = 0; c < 4; c++){
        int pi = c*8 + eh_e;
        if (pi < deg) sAlpha[wd][pi*4 + eh_h] = ev[c]*invs;
    }
    __syncwarp();

    // ---- phase 3: aggregate over features ----
    int head = lane >> 3;
    float invs_h = __shfl_sync(0xffffffffu, invs, head);
    float mx_h   = __shfl_sync(0xffffffffu, mx,   head);
    float er_hh  = __shfl_sync(0xffffffffu, er_h, head);

    float4 acc = *(const float4*)&bias[lane*4];
    float4 c4, d4;
    if (MODE == 1){
        c4 = *(const float4*)&g_c[lane*4];
        d4 = *(const float4*)&g_d[lane*4];
    }
    int lim = deg < 32 ? deg : 32;
    for (int p = 0; p < lim; p++){
        int s   = sSrc[wd][p];
        float w = sAlpha[wd][p*4 + head];
        if (MODE == 1){
            float ws = weights[s];
            acc.x += (ws*c4.x + d4.x)*w;
            acc.y += (ws*c4.y + d4.y)*w;
            acc.z += (ws*c4.z + d4.z)*w;
            acc.w += (ws*c4.w + d4.w)*w;
        } else {
            float4 hv = *(const float4*)&g_h[(size_t)s*DD + lane*4];
            acc.x += hv.x*w; acc.y += hv.y*w; acc.z += hv.z*w; acc.w += hv.w*w;
        }
    }
    for (int p = 32; p < deg; p++){                       // rare overflow
        int s = g_csrc[start + p];
        float w = __expf(lrelu02(g_el[s*4 + head] + er_hh) - mx_h) * invs_h;
        if (MODE == 1){
            float ws = weights[s];
            acc.x += (ws*c4.x + d4.x)*w;
            acc.y += (ws*c4.y + d4.y)*w;
            acc.z += (ws*c4.z + d4.z)*w;
            acc.w += (ws*c4.w + d4.w)*w;
        } else {
            float4 hv = *(const float4*)&g_h[(size_t)s*DD + lane*4];
            acc.x += hv.x*w; acc.y += hv.y*w; acc.z += hv.z*w; acc.w += hv.w*w;
        }
    }

    if (MODE == 2){
        float4 wv = *(const float4*)&pw[lane*4];
        float sdot = acc.x*wv.x + acc.y*wv.y + acc.z*wv.z + acc.w*wv.w;
        #pragma unroll
        for (int o = 16; o; o >>= 1) sdot += __shfl_down_sync(0xffffffffu, sdot, o);
        if (lane == 0) out[wid] = sdot + pb[0];
    } else {
        *(float4*)&g_x[(size_t)wid*DD + lane*4] = acc;
    }
}

__global__ void k_smax_aggr(const float* __restrict__ bias){
    smax_aggr_body<0>(bias, nullptr, nullptr, nullptr, nullptr);
}
__global__ void k_smax_aggr0(const float* __restrict__ weights,
                             const float* __restrict__ bias){
    smax_aggr_body<1>(bias, weights, nullptr, nullptr, nullptr);
}
__global__ void k_smax_aggr_pred(const float* __restrict__ bias,
                                 const float* __restrict__ pw,
                                 const float* __restrict__ pb,
                                 float* __restrict__ out){
    smax_aggr_body<2>(bias, nullptr, pw, pb, out);
}

// ---------------- launch ----------------------------------------------------
// NOTE: never pass __device__ symbols as kernel arguments from host code —
// on GB300 (ATS) that silently binds the HOST shadow variable.
extern "C" void kernel_launch(void* const* d_in, const int* in_sizes, int n_in,
                              void* d_out, int out_size){
    const float* weights = (const float*)d_in[0];
    const float* lin_W   = (const float*)d_in[1];
    const float* lin_b   = (const float*)d_in[2];
    const float* fc_W    = (const float*)d_in[3];
    const float* attn_l  = (const float*)d_in[4];
    const float* attn_r  = (const float*)d_in[5];
    const float* conv_b  = (const float*)d_in[6];
    const float* pred_W  = (const float*)d_in[7];
    const float* pred_b  = (const float*)d_in[8];
    const int*   src     = (const int*)d_in[9];
    const int*   dst     = (const int*)d_in[10];
    float* out = (float*)d_out;

    static int smem_set = 0;
    if (!smem_set){
        cudaFuncSetAttribute(k_hgemm, cudaFuncAttributeMaxDynamicSharedMemorySize, SM_BYTES);
        smem_set = 1;
    }

    // --- CSR build (once per launch) ---
    k_init_deg<<<(NN+255)/256, 256>>>();
    k_hist<<<(EE+255)/256, 256>>>(dst);
    k_scan1<<<98, 1024>>>();
    k_scan2<<<1, 128>>>();
    k_scan3<<<98, 1024>>>();
    k_fill<<<(ETOT+255)/256, 256>>>(src, dst);

    // --- layer 0 (rank-1 features) ---
    k_l0prep<<<1, 128>>>(lin_W, lin_b, fc_W, attn_l, attn_r);
    k_l0_eler<<<(NB4+255)/256, 256>>>(weights);
    k_smax_aggr0<<<(NN*32+255)/256, 256>>>(weights, conv_b);

    // --- layer 1 (HMMA GEMM fuses el/er epilogue) ---
    k_hgemm<<<NNP/128, 256, SM_BYTES>>>(fc_W + 1*DD*DD, attn_l + 1*DD, attn_r + 1*DD);
    k_smax_aggr<<<(NN*32+255)/256, 256>>>(conv_b + 1*DD);

    // --- layer 2 ---
    k_hgemm<<<NNP/128, 256, SM_BYTES>>>(fc_W + 2*DD*DD, attn_l + 2*DD, attn_r + 2*DD);
    k_smax_aggr_pred<<<(NN*32+255)/256, 256>>>(conv_b + 2*DD, pred_W, pred_b, out);
}

// round 9
// speedup vs baseline: 5.8974x; 1.0104x over previous
#include <cuda_runtime.h>
#include <cuda_bf16.h>
#include <cstdint>

#define NN   100000
#define NNP  100096          // 782 * 128 (row-padded for GEMM tiles)
#define EE   600000
#define DD   128
#define HH   4
#define FF   32
#define NB4  (NN*4)

typedef unsigned long long ull;

// ---------------- scratch: device symbols, used ONLY inside device code ----
__device__ __align__(256) float g_x[NNP*DD];   // current node features
__device__ __align__(256) float g_h[NNP*DD];   // fc output of current layer
__device__ __align__(256) float g_el[NB4];
__device__ __align__(256) float g_er[NB4];
__device__ __align__(256) int   g_deg[NN];     // WITHOUT self loop
__device__ __align__(256) int   g_off[NN];
__device__ __align__(256) int   g_cur[NN];
__device__ __align__(256) int   g_bsum[128];
__device__ __align__(256) int   g_csrc[EE];
__device__ __align__(256) float g_c[DD];
__device__ __align__(256) float g_d[DD];
__device__ float g_cl[HH], g_dl[HH], g_cr[HH], g_dr[HH];

__device__ __forceinline__ float lrelu02(float x){ return (x >= 0.f) ? x : 0.2f*x; }

// bf16 hi/lo split of two floats -> packed bf16x2 words
__device__ __forceinline__ uint32_t bfsplit2(float x0, float x1, uint32_t& lo){
    __nv_bfloat16 h0 = __float2bfloat16(x0);
    __nv_bfloat16 h1 = __float2bfloat16(x1);
    float r0 = x0 - __bfloat162float(h0);
    float r1 = x1 - __bfloat162float(h1);
    __nv_bfloat16 g0 = __float2bfloat16(r0);
    __nv_bfloat16 g1 = __float2bfloat16(r1);
    lo = (uint32_t)__bfloat16_as_ushort(g0) | ((uint32_t)__bfloat16_as_ushort(g1) << 16);
    return (uint32_t)__bfloat16_as_ushort(h0) | ((uint32_t)__bfloat16_as_ushort(h1) << 16);
}

// warp-level bf16 MMA (baseline sm_80+ PTX; compiles at compute_103)
#define MMA_BF16(d, a, b0, b1) \
    asm volatile("mma.sync.aligned.m16n8k16.row.col.f32.bf16.bf16.f32 " \
        "{%0,%1,%2,%3}, {%4,%5,%6,%7}, {%8,%9}, {%0,%1,%2,%3};" \
        : "+f"((d)[0]), "+f"((d)[1]), "+f"((d)[2]), "+f"((d)[3]) \
        : "r"((a)[0]), "r"((a)[1]), "r"((a)[2]), "r"((a)[3]), "r"(b0), "r"(b1))

// ---------------- init: zero deg + (block 0) layer-0 rank-1 prep ------------
__global__ void k_init(const float* __restrict__ linW, const float* __restrict__ linb,
                       const float* __restrict__ W0,
                       const float* __restrict__ al0, const float* __restrict__ ar0){
    int i = blockIdx.x*blockDim.x + threadIdx.x;
    if (i < NN) g_deg[i] = 0;
    if (blockIdx.x == 0 && threadIdx.x < 128){
        int j = threadIdx.x;
        float c = 0.f, d = 0.f;
        const float* wr = W0 + j*DD;
        #pragma unroll 8
        for (int k = 0; k < DD; k++){
            float w = wr[k];
            c += linW[k]*w;
            d += linb[k]*w;
        }
        g_c[j] = c; g_d[j] = d;
        float alv = al0[j], arv = ar0[j];
        float cl = c*alv, dl = d*alv, cr = c*arv, dr = d*arv;
        #pragma unroll
        for (int o = 16; o; o >>= 1){
            cl += __shfl_down_sync(0xffffffffu, cl, o);
            dl += __shfl_down_sync(0xffffffffu, dl, o);
            cr += __shfl_down_sync(0xffffffffu, cr, o);
            dr += __shfl_down_sync(0xffffffffu, dr, o);
        }
        int lane = j & 31, hd = j >> 5;
        if (lane == 0){ g_cl[hd]=cl; g_dl[hd]=dl; g_cr[hd]=cr; g_dr[hd]=dr; }
    }
}

__global__ void k_hist(const int* __restrict__ dst){
    int i = blockIdx.x*blockDim.x + threadIdx.x;
    if (i < EE) atomicAdd(&g_deg[dst[i]], 1);
}

__global__ void k_scan1(){                    // per-1024-block sums of deg
    int i = blockIdx.x*1024 + threadIdx.x;
    int v = (i < NN) ? g_deg[i] : 0;
    __shared__ int sh[32];
    int lane = threadIdx.x & 31, wd = threadIdx.x >> 5;
    #pragma unroll
    for (int o = 16; o; o >>= 1) v += __shfl_down_sync(0xffffffffu, v, o);
    if (lane == 0) sh[wd] = v;
    __syncthreads();
    if (wd == 0){
        int s = sh[lane];
        #pragma unroll
        for (int o = 16; o; o >>= 1) s += __shfl_down_sync(0xffffffffu, s, o);
        if (lane == 0) g_bsum[blockIdx.x] = s;
    }
}

// per-block exclusive scan; block base = sum of preceding raw block sums
__global__ void k_scan23(){
    __shared__ int sbase;
    __shared__ int sh[32];
    int lane = threadIdx.x & 31, wd = threadIdx.x >> 5;
    if (wd == 0){
        int s = 0;
        for (int j = lane; j < blockIdx.x; j += 32) s += g_bsum[j];
        #pragma unroll
        for (int o = 16; o; o >>= 1) s += __shfl_down_sync(0xffffffffu, s, o);
        if (lane == 0) sbase = s;
    }
    int i = blockIdx.x*1024 + threadIdx.x;
    int v = (i < NN) ? g_deg[i] : 0;
    int orig = v;
    #pragma unroll
    for (int o = 1; o < 32; o <<= 1){
        int u = __shfl_up_sync(0xffffffffu, v, o);
        if (lane >= o) v += u;
    }
    if (lane == 31) sh[wd] = v;
    __syncthreads();
    if (wd == 0){
        int s = sh[lane];
        #pragma unroll
        for (int o = 1; o < 32; o <<= 1){
            int u = __shfl_up_sync(0xffffffffu, s, o);
            if (lane >= o) s += u;
        }
        sh[lane] = s;
    }
    __syncthreads();
    int add = ((wd > 0) ? sh[wd-1] : 0) + sbase;
    int excl = v - orig + add;
    if (i < NN){ g_off[i] = excl; g_cur[i] = excl; }
}

__global__ void k_fill(const int* __restrict__ src, const int* __restrict__ dst){
    int i = blockIdx.x*blockDim.x + threadIdx.x;
    if (i < EE){
        int d = dst[i];
        int pos = atomicAdd(&g_cur[d], 1);
        g_csrc[pos] = src[i];
    }
}

// ---------------- HMMA split-bf16 GEMM + fused el/er (layers 1,2) ----------
// g_h = leaky(g_x) @ W^T ; h = Ahi*Whi + Ahi*Wlo + Alo*Whi (fp32 accum)
#define WP 68
#define SM_WORDS (4*128*WP)
#define SM_BYTES (SM_WORDS*4)

__global__ void __launch_bounds__(256)
k_hgemm(const float* __restrict__ W,
        const float* __restrict__ al, const float* __restrict__ ar){
    extern __shared__ __align__(16) uint32_t sm[];
    uint32_t* Whi = sm;
    uint32_t* Wlo = sm + 128*WP;
    uint32_t* Xhi = sm + 2*128*WP;
    uint32_t* Xlo = sm + 3*128*WP;
    float*    stagef = (float*)(sm + 2*128*WP);   // aliases Xhi/Xlo (after sync)

    int tid  = threadIdx.x;
    int w    = tid >> 5;
    int lane = tid & 31;
    int qr   = lane >> 2, qc = lane & 3;
    int row0 = blockIdx.x * 128;
    int rw   = w * 16;

    // ---- convert W and x tiles to split-bf16 smem ----
    {
        const float4* ws = (const float4*)W;
        const float4* xs = (const float4*)&g_x[(size_t)row0*DD];
        #pragma unroll 4
        for (int j = 0; j < 16; j++){
            int idx = j*256 + tid;                 // float4 index (4096 total)
            int r = idx >> 5, c4 = idx & 31;
            float4 v = ws[idx];
            uint32_t lo0, lo1;
            uint32_t hi0 = bfsplit2(v.x, v.y, lo0);
            uint32_t hi1 = bfsplit2(v.z, v.w, lo1);
            Whi[r*WP + c4*2]     = hi0; Whi[r*WP + c4*2 + 1] = hi1;
            Wlo[r*WP + c4*2]     = lo0; Wlo[r*WP + c4*2 + 1] = lo1;
            float4 u = xs[idx];
            u.x = (u.x >= 0.f) ? u.x : 0.01f*u.x;
            u.y = (u.y >= 0.f) ? u.y : 0.01f*u.y;
            u.z = (u.z >= 0.f) ? u.z : 0.01f*u.z;
            u.w = (u.w >= 0.f) ? u.w : 0.01f*u.w;
            uint32_t xh0 = bfsplit2(u.x, u.y, lo0);
            uint32_t xh1 = bfsplit2(u.z, u.w, lo1);
            Xhi[r*WP + c4*2]     = xh0; Xhi[r*WP + c4*2 + 1] = xh1;
            Xlo[r*WP + c4*2]     = lo0; Xlo[r*WP + c4*2 + 1] = lo1;
        }
    }
    __syncthreads();

    // ---- compute: warp w owns rows rw..rw+15, all 128 cols ----
    float acc[16][4];
    #pragma unroll
    for (int nt = 0; nt < 16; nt++)
        #pragma unroll
        for (int i = 0; i < 4; i++) acc[nt][i] = 0.f;

    #pragma unroll
    for (int ks = 0; ks < 8; ks++){
        int abase = (rw + qr)*WP + ks*8 + qc;
        uint32_t ahi[4], alo[4];
        ahi[0] = Xhi[abase];          ahi[1] = Xhi[abase + 8*WP];
        ahi[2] = Xhi[abase + 4];      ahi[3] = Xhi[abase + 8*WP + 4];
        alo[0] = Xlo[abase];          alo[1] = Xlo[abase + 8*WP];
        alo[2] = Xlo[abase + 4];      alo[3] = Xlo[abase + 8*WP + 4];
        #pragma unroll
        for (int nt = 0; nt < 16; nt++){
            int bbase = (nt*8 + qr)*WP + ks*8 + qc;
            uint32_t bh0 = Whi[bbase], bh1 = Whi[bbase + 4];
            uint32_t bl0 = Wlo[bbase], bl1 = Wlo[bbase + 4];
            MMA_BF16(acc[nt], ahi, bh0, bh1);
            MMA_BF16(acc[nt], ahi, bl0, bl1);
            MMA_BF16(acc[nt], alo, bh0, bh1);
        }
    }
    __syncthreads();                              // all warps done reading X smem

    // ---- epilogue: stage h + el/er from fragments ----
    float sl0[4], sr0[4], sl1[4], sr1[4];
    #pragma unroll
    for (int h = 0; h < 4; h++){ sl0[h]=0.f; sr0[h]=0.f; sl1[h]=0.f; sr1[h]=0.f; }
    #pragma unroll
    for (int nt = 0; nt < 16; nt++){
        int col = nt*8 + qc*2;
        float c0 = acc[nt][0], c1 = acc[nt][1], c2 = acc[nt][2], c3 = acc[nt][3];
        *(float2*)&stagef[(rw+qr)*132 + col]   = make_float2(c0, c1);
        *(float2*)&stagef[(rw+qr+8)*132 + col] = make_float2(c2, c3);
        float2 alv = *(const float2*)&al[col];
        float2 arv = *(const float2*)&ar[col];
        int h = nt >> 2;
        sl0[h] += c0*alv.x + c1*alv.y;  sr0[h] += c0*arv.x + c1*arv.y;
        sl1[h] += c2*alv.x + c3*alv.y;  sr1[h] += c2*arv.x + c3*arv.y;
    }
    #pragma unroll
    for (int h = 0; h < 4; h++){
        sl0[h] += __shfl_xor_sync(0xffffffffu, sl0[h], 1);
        sl0[h] += __shfl_xor_sync(0xffffffffu, sl0[h], 2);
        sr0[h] += __shfl_xor_sync(0xffffffffu, sr0[h], 1);
        sr0[h] += __shfl_xor_sync(0xffffffffu, sr0[h], 2);
        sl1[h] += __shfl_xor_sync(0xffffffffu, sl1[h], 1);
        sl1[h] += __shfl_xor_sync(0xffffffffu, sl1[h], 2);
        sr1[h] += __shfl_xor_sync(0xffffffffu, sr1[h], 1);
        sr1[h] += __shfl_xor_sync(0xffffffffu, sr1[h], 2);
    }
    if (qc == 0){
        int r0 = row0 + rw + qr;
        int r1 = r0 + 8;
        if (r0 < NN){
            #pragma unroll
            for (int h = 0; h < 4; h++){ g_el[r0*4+h] = sl0[h]; g_er[r0*4+h] = sr0[h]; }
        }
        if (r1 < NN){
            #pragma unroll
            for (int h = 0; h < 4; h++){ g_el[r1*4+h] = sl1[h]; g_er[r1*4+h] = sr1[h]; }
        }
    }
    __syncthreads();

    // ---- coalesced h writeback ----
    {
        float4* hd = (float4*)&g_h[(size_t)row0*DD];
        #pragma unroll 4
        for (int j = 0; j < 16; j++){
            int idx = j*256 + tid;
            int r = idx >> 5, c4 = idx & 31;
            hd[idx] = *(const float4*)&stagef[r*132 + c4*4];
        }
    }
}

// ---------------- fused edge-softmax + aggregation (warp per node) ---------
// self loop handled analytically (not in CSR). MODE: 0 = g_h gather,
// 1 = layer-0 rank-1 (el/er from weights inline), 2 = g_h + prediction head
template<int MODE>
__device__ __forceinline__ void smax_aggr_body(
    const float* __restrict__ bias, const float* __restrict__ weights,
    const float* __restrict__ pw, const float* __restrict__ pb,
    float* __restrict__ out)
{
    int wid = (blockIdx.x*blockDim.x + threadIdx.x) >> 5;
    if (wid >= NN) return;
    int lane = threadIdx.x & 31;
    int wd   = (threadIdx.x >> 5) & 7;
    __shared__ float sAlpha[8][128];
    __shared__ int   sSrc[8][32];

    int start = g_off[wid];
    int deg   = g_deg[wid];                  // excludes self

    // ---- phase 1: e + max (lanes over (edge,head)) ----
    int eh_e = lane >> 2;                    // edge slot within chunk (0..7)
    int eh_h = lane & 3;                     // head
    float wself, er_h, e_self;
    if (MODE == 1){
        wself = weights[wid];
        er_h  = wself*g_cr[eh_h] + g_dr[eh_h];
        e_self = lrelu02(wself*g_cl[eh_h] + g_dl[eh_h] + er_h);
    } else {
        wself = 0.f;
        er_h  = g_er[wid*4 + eh_h];
        e_self = lrelu02(g_el[wid*4 + eh_h] + er_h);
    }
    float ev[4];
    float mx = e_self;
    #pragma unroll
    for (int c = 0; c < 4; c++){
        int pi = c*8 + eh_e;
        float e = -3.0e38f;
        if (pi < deg){
            int s = g_csrc[start + pi];
            if (eh_h == 0) sSrc[wd][pi] = s;
            float els = (MODE == 1) ? (weights[s]*g_cl[eh_h] + g_dl[eh_h])
                                    : g_el[s*4 + eh_h];
            e = lrelu02(els + er_h);
        }
        ev[c] = e;
        mx = fmaxf(mx, e);
    }
    for (int pi = 32 + eh_e; pi < deg; pi += 8){          // rare overflow
        int s = g_csrc[start + pi];
        float els = (MODE == 1) ? (weights[s]*g_cl[eh_h] + g_dl[eh_h])
                                : g_el[s*4 + eh_h];
        mx = fmaxf(mx, lrelu02(els + er_h));
    }
    mx = fmaxf(mx, __shfl_xor_sync(0xffffffffu, mx, 4));
    mx = fmaxf(mx, __shfl_xor_sync(0xffffffffu, mx, 8));
    mx = fmaxf(mx, __shfl_xor_sync(0xffffffffu, mx, 16));

    // ---- phase 2: exp + sum ----
    float sum = (eh_e == 0) ? __expf(e_self - mx) : 0.f;
    #pragma unroll
    for (int c = 0; c < 4; c++){
        int pi = c*8 + eh_e;
        float a = 0.f;
        if (pi < deg) a = __expf(ev[c] - mx);
        ev[c] = a;
        sum += a;
    }
    for (int pi = 32 + eh_e; pi < deg; pi += 8){          // rare overflow
        int s = g_csrc[start + pi];
        float els = (MODE == 1) ? (weights[s]*g_cl[eh_h] + g_dl[eh_h])
                                : g_el[s*4 + eh_h];
        sum += __expf(lrelu02(els + er_h) - mx);
    }
    sum += __shfl_xor_sync(0xffffffffu, sum, 4);
    sum += __shfl_xor_sync(0xffffffffu, sum, 8);
    sum += __shfl_xor_sync(0xffffffffu, sum, 16);
    float invs = 1.0f / sum;

    #pragma unroll
    for (int c = 0; c < 4; c++){
        int pi = c*8 + eh_e;
        if (pi < deg && pi < 32) sAlpha[wd][pi*4 + eh_h] = ev[c]*invs;
    }
    __syncwarp();

    // ---- phase 3: aggregate over features ----
    int head = lane >> 3;
    float invs_h   = __shfl_sync(0xffffffffu, invs,   head);
    float mx_h     = __shfl_sync(0xffffffffu, mx,     head);
    float er_hh    = __shfl_sync(0xffffffffu, er_h,   head);
    float e_self_h = __shfl_sync(0xffffffffu, e_self, head);

    float4 acc = *(const float4*)&bias[lane*4];
    float4 c4, d4;
    if (MODE == 1){
        c4 = *(const float4*)&g_c[lane*4];
        d4 = *(const float4*)&g_d[lane*4];
    }
    // self contribution
    {
        float a_self = __expf(e_self_h - mx_h) * invs_h;
        if (MODE == 1){
            acc.x += (wself*c4.x + d4.x)*a_self;
            acc.y += (wself*c4.y + d4.y)*a_self;
            acc.z += (wself*c4.z + d4.z)*a_self;
            acc.w += (wself*c4.w + d4.w)*a_self;
        } else {
            float4 hv = *(const float4*)&g_h[(size_t)wid*DD + lane*4];
            acc.x += hv.x*a_self; acc.y += hv.y*a_self;
            acc.z += hv.z*a_self; acc.w += hv.w*a_self;
        }
    }
    int lim = deg < 32 ? deg : 32;
    for (int p = 0; p < lim; p++){
        int s   = sSrc[wd][p];
        float w = sAlpha[wd][p*4 + head];
        if (MODE == 1){
            float ws = weights[s];
            acc.x += (ws*c4.x + d4.x)*w;
            acc.y += (ws*c4.y + d4.y)*w;
            acc.z += (ws*c4.z + d4.z)*w;
            acc.w += (ws*c4.w + d4.w)*w;
        } else {
            float4 hv = *(const float4*)&g_h[(size_t)s*DD + lane*4];
            acc.x += hv.x*w; acc.y += hv.y*w; acc.z += hv.z*w; acc.w += hv.w*w;
        }
    }
    for (int p = 32; p < deg; p++){                       // rare overflow
        int s = g_csrc[start + p];
        float els = (MODE == 1) ? (weights[s]*g_cl[head] + g_dl[head])
                                : g_el[s*4 + head];
        float w = __expf(lrelu02(els + er_hh) - mx_h) * invs_h;
        if (MODE == 1){
            float ws = weights[s];
            acc.x += (ws*c4.x + d4.x)*w;
            acc.y += (ws*c4.y + d4.y)*w;
            acc.z += (ws*c4.z + d4.z)*w;
            acc.w += (ws*c4.w + d4.w)*w;
        } else {
            float4 hv = *(const float4*)&g_h[(size_t)s*DD + lane*4];
            acc.x += hv.x*w; acc.y += hv.y*w; acc.z += hv.z*w; acc.w += hv.w*w;
        }
    }

    if (MODE == 2){
        float4 wv = *(const float4*)&pw[lane*4];
        float sdot = acc.x*wv.x + acc.y*wv.y + acc.z*wv.z + acc.w*wv.w;
        #pragma unroll
        for (int o = 16; o; o >>= 1) sdot += __shfl_down_sync(0xffffffffu, sdot, o);
        if (lane == 0) out[wid] = sdot + pb[0];
    } else {
        *(float4*)&g_x[(size_t)wid*DD + lane*4] = acc;
    }
}

__global__ void k_smax_aggr(const float* __restrict__ bias){
    smax_aggr_body<0>(bias, nullptr, nullptr, nullptr, nullptr);
}
__global__ void k_smax_aggr0(const float* __restrict__ weights,
                             const float* __restrict__ bias){
    smax_aggr_body<1>(bias, weights, nullptr, nullptr, nullptr);
}
__global__ void k_smax_aggr_pred(const float* __restrict__ bias,
                                 const float* __restrict__ pw,
                                 const float* __restrict__ pb,
                                 float* __restrict__ out){
    smax_aggr_body<2>(bias, nullptr, pw, pb, out);
}

// ---------------- launch ----------------------------------------------------
// NOTE: never pass __device__ symbols as kernel arguments from host code —
// on GB300 (ATS) that silently binds the HOST shadow variable.
extern "C" void kernel_launch(void* const* d_in, const int* in_sizes, int n_in,
                              void* d_out, int out_size){
    const float* weights = (const float*)d_in[0];
    const float* lin_W   = (const float*)d_in[1];
    const float* lin_b   = (const float*)d_in[2];
    const float* fc_W    = (const float*)d_in[3];
    const float* attn_l  = (const float*)d_in[4];
    const float* attn_r  = (const float*)d_in[5];
    const float* conv_b  = (const float*)d_in[6];
    const float* pred_W  = (const float*)d_in[7];
    const float* pred_b  = (const float*)d_in[8];
    const int*   src     = (const int*)d_in[9];
    const int*   dst     = (const int*)d_in[10];
    float* out = (float*)d_out;

    static int smem_set = 0;
    if (!smem_set){
        cudaFuncSetAttribute(k_hgemm, cudaFuncAttributeMaxDynamicSharedMemorySize, SM_BYTES);
        smem_set = 1;
    }

    // --- CSR build (no self loops) + layer-0 prep fused into k_init ---
    k_init<<<(NN+255)/256, 256>>>(lin_W, lin_b, fc_W, attn_l, attn_r);
    k_hist<<<(EE+255)/256, 256>>>(dst);
    k_scan1<<<98, 1024>>>();
    k_scan23<<<98, 1024>>>();
    k_fill<<<(EE+255)/256, 256>>>(src, dst);

    // --- layer 0 (rank-1 features; el/er computed inline) ---
    k_smax_aggr0<<<(NN*32+255)/256, 256>>>(weights, conv_b);

    // --- layer 1 (HMMA GEMM fuses el/er epilogue) ---
    k_hgemm<<<NNP/128, 256, SM_BYTES>>>(fc_W + 1*DD*DD, attn_l + 1*DD, attn_r + 1*DD);
    k_smax_aggr<<<(NN*32+255)/256, 256>>>(conv_b + 1*DD);

    // --- layer 2 ---
    k_hgemm<<<NNP/128, 256, SM_BYTES>>>(fc_W + 2*DD*DD, attn_l + 2*DD, attn_r + 2*DD);
    k_smax_aggr_pred<<<(NN*32+255)/256, 256>>>(conv_b + 2*DD, pred_W, pred_b, out);
}

// round 11
// speedup vs baseline: 5.9739x; 1.0130x over previous
#include <cuda_runtime.h>
#include <cuda_bf16.h>
#include <cstdint>

#define NN   100000
#define NNP  100096          // 782 * 128 (row-padded for GEMM tiles)
#define EE   600000
#define DD   128
#define HH   4
#define FF   32
#define NB4  (NN*4)
#define BKT  64              // bucket slots per node (P(deg>64) ~ 1e-40)

typedef unsigned long long ull;

// ---------------- scratch: device symbols, used ONLY inside device code ----
__device__ __align__(256) float g_x[NNP*DD];   // current node features
__device__ __align__(256) float g_h[NNP*DD];   // fc output of current layer
__device__ __align__(256) float g_el[NB4];
__device__ __align__(256) float g_er[NB4];
__device__ __align__(256) int   g_deg[NN];     // WITHOUT self loop
__device__ __align__(256) int   g_csrc[NN*BKT];
__device__ __align__(256) float g_c[DD];
__device__ __align__(256) float g_d[DD];
__device__ float g_cl[HH], g_dl[HH], g_cr[HH], g_dr[HH];

__device__ __forceinline__ float lrelu02(float x){ return (x >= 0.f) ? x : 0.2f*x; }

// bf16 hi/lo split of two floats -> packed bf16x2 words
__device__ __forceinline__ uint32_t bfsplit2(float x0, float x1, uint32_t& lo){
    __nv_bfloat16 h0 = __float2bfloat16(x0);
    __nv_bfloat16 h1 = __float2bfloat16(x1);
    float r0 = x0 - __bfloat162float(h0);
    float r1 = x1 - __bfloat162float(h1);
    __nv_bfloat16 g0 = __float2bfloat16(r0);
    __nv_bfloat16 g1 = __float2bfloat16(r1);
    lo = (uint32_t)__bfloat16_as_ushort(g0) | ((uint32_t)__bfloat16_as_ushort(g1) << 16);
    return (uint32_t)__bfloat16_as_ushort(h0) | ((uint32_t)__bfloat16_as_ushort(h1) << 16);
}

// warp-level bf16 MMA (baseline sm_80+ PTX; compiles at compute_103)
#define MMA_BF16(d, a, b0, b1) \
    asm volatile("mma.sync.aligned.m16n8k16.row.col.f32.bf16.bf16.f32 " \
        "{%0,%1,%2,%3}, {%4,%5,%6,%7}, {%8,%9}, {%0,%1,%2,%3};" \
        : "+f"((d)[0]), "+f"((d)[1]), "+f"((d)[2]), "+f"((d)[3]) \
        : "r"((a)[0]), "r"((a)[1]), "r"((a)[2]), "r"((a)[3]), "r"(b0), "r"(b1))

// ---------------- init: zero deg + (block 0) layer-0 rank-1 prep ------------
__global__ void k_init(const float* __restrict__ linW, const float* __restrict__ linb,
                       const float* __restrict__ W0,
                       const float* __restrict__ al0, const float* __restrict__ ar0){
    int i = blockIdx.x*blockDim.x + threadIdx.x;
    if (i < NN) g_deg[i] = 0;
    if (blockIdx.x == 0 && threadIdx.x < 128){
        int j = threadIdx.x;
        float c = 0.f, d = 0.f;
        const float* wr = W0 + j*DD;
        #pragma unroll 8
        for (int k = 0; k < DD; k++){
            float w = wr[k];
            c += linW[k]*w;
            d += linb[k]*w;
        }
        g_c[j] = c; g_d[j] = d;
        float alv = al0[j], arv = ar0[j];
        float cl = c*alv, dl = d*alv, cr = c*arv, dr = d*arv;
        #pragma unroll
        for (int o = 16; o; o >>= 1){
            cl += __shfl_down_sync(0xffffffffu, cl, o);
            dl += __shfl_down_sync(0xffffffffu, dl, o);
            cr += __shfl_down_sync(0xffffffffu, cr, o);
            dr += __shfl_down_sync(0xffffffffu, dr, o);
        }
        int lane = j & 31, hd = j >> 5;
        if (lane == 0){ g_cl[hd]=cl; g_dl[hd]=dl; g_cr[hd]=cr; g_dr[hd]=dr; }
    }
}

// ---------------- bucket fill: hist + fill fused (no scan needed) -----------
__global__ void k_fillbucket(const int* __restrict__ src, const int* __restrict__ dst){
    int i = blockIdx.x*blockDim.x + threadIdx.x;
    if (i < EE){
        int d = dst[i];
        int pos = atomicAdd(&g_deg[d], 1);
        if (pos < BKT) g_csrc[d*BKT + pos] = src[i];
    }
}

// ---------------- HMMA split-bf16 GEMM + fused el/er (layers 1,2) ----------
// g_h = leaky(g_x) @ W^T ; h = Ahi*Whi + Ahi*Wlo + Alo*Whi (fp32 accum)
#define WP 68
#define SM_WORDS (4*128*WP)
#define SM_BYTES (SM_WORDS*4)

__global__ void __launch_bounds__(256)
k_hgemm(const float* __restrict__ W,
        const float* __restrict__ al, const float* __restrict__ ar){
    extern __shared__ __align__(16) uint32_t sm[];
    uint32_t* Whi = sm;
    uint32_t* Wlo = sm + 128*WP;
    uint32_t* Xhi = sm + 2*128*WP;
    uint32_t* Xlo = sm + 3*128*WP;
    float*    stagef = (float*)(sm + 2*128*WP);   // aliases Xhi/Xlo (after sync)

    int tid  = threadIdx.x;
    int w    = tid >> 5;
    int lane = tid & 31;
    int qr   = lane >> 2, qc = lane & 3;
    int row0 = blockIdx.x * 128;
    int rw   = w * 16;

    // ---- convert W and x tiles to split-bf16 smem ----
    {
        const float4* ws = (const float4*)W;
        const float4* xs = (const float4*)&g_x[(size_t)row0*DD];
        #pragma unroll 4
        for (int j = 0; j < 16; j++){
            int idx = j*256 + tid;                 // float4 index (4096 total)
            int r = idx >> 5, c4 = idx & 31;
            float4 v = ws[idx];
            uint32_t lo0, lo1;
            uint32_t hi0 = bfsplit2(v.x, v.y, lo0);
            uint32_t hi1 = bfsplit2(v.z, v.w, lo1);
            Whi[r*WP + c4*2]     = hi0; Whi[r*WP + c4*2 + 1] = hi1;
            Wlo[r*WP + c4*2]     = lo0; Wlo[r*WP + c4*2 + 1] = lo1;
            float4 u = xs[idx];
            u.x = (u.x >= 0.f) ? u.x : 0.01f*u.x;
            u.y = (u.y >= 0.f) ? u.y : 0.01f*u.y;
            u.z = (u.z >= 0.f) ? u.z : 0.01f*u.z;
            u.w = (u.w >= 0.f) ? u.w : 0.01f*u.w;
            uint32_t xh0 = bfsplit2(u.x, u.y, lo0);
            uint32_t xh1 = bfsplit2(u.z, u.w, lo1);
            Xhi[r*WP + c4*2]     = xh0; Xhi[r*WP + c4*2 + 1] = xh1;
            Xlo[r*WP + c4*2]     = lo0; Xlo[r*WP + c4*2 + 1] = lo1;
        }
    }
    __syncthreads();

    // ---- compute: warp w owns rows rw..rw+15, all 128 cols ----
    float acc[16][4];
    #pragma unroll
    for (int nt = 0; nt < 16; nt++)
        #pragma unroll
        for (int i = 0; i < 4; i++) acc[nt][i] = 0.f;

    #pragma unroll
    for (int ks = 0; ks < 8; ks++){
        int abase = (rw + qr)*WP + ks*8 + qc;
        uint32_t ahi[4], alo[4];
        ahi[0] = Xhi[abase];          ahi[1] = Xhi[abase + 8*WP];
        ahi[2] = Xhi[abase + 4];      ahi[3] = Xhi[abase + 8*WP + 4];
        alo[0] = Xlo[abase];          alo[1] = Xlo[abase + 8*WP];
        alo[2] = Xlo[abase + 4];      alo[3] = Xlo[abase + 8*WP + 4];
        #pragma unroll
        for (int nt = 0; nt < 16; nt++){
            int bbase = (nt*8 + qr)*WP + ks*8 + qc;
            uint32_t bh0 = Whi[bbase], bh1 = Whi[bbase + 4];
            uint32_t bl0 = Wlo[bbase], bl1 = Wlo[bbase + 4];
            MMA_BF16(acc[nt], ahi, bh0, bh1);
            MMA_BF16(acc[nt], ahi, bl0, bl1);
            MMA_BF16(acc[nt], alo, bh0, bh1);
        }
    }
    __syncthreads();                              // all warps done reading X smem

    // ---- epilogue: stage h + el/er from fragments ----
    float sl0[4], sr0[4], sl1[4], sr1[4];
    #pragma unroll
    for (int h = 0; h < 4; h++){ sl0[h]=0.f; sr0[h]=0.f; sl1[h]=0.f; sr1[h]=0.f; }
    #pragma unroll
    for (int nt = 0; nt < 16; nt++){
        int col = nt*8 + qc*2;
        float c0 = acc[nt][0], c1 = acc[nt][1], c2 = acc[nt][2], c3 = acc[nt][3];
        *(float2*)&stagef[(rw+qr)*132 + col]   = make_float2(c0, c1);
        *(float2*)&stagef[(rw+qr+8)*132 + col] = make_float2(c2, c3);
        float2 alv = *(const float2*)&al[col];
        float2 arv = *(const float2*)&ar[col];
        int h = nt >> 2;
        sl0[h] += c0*alv.x + c1*alv.y;  sr0[h] += c0*arv.x + c1*arv.y;
        sl1[h] += c2*alv.x + c3*alv.y;  sr1[h] += c2*arv.x + c3*arv.y;
    }
    #pragma unroll
    for (int h = 0; h < 4; h++){
        sl0[h] += __shfl_xor_sync(0xffffffffu, sl0[h], 1);
        sl0[h] += __shfl_xor_sync(0xffffffffu, sl0[h], 2);
        sr0[h] += __shfl_xor_sync(0xffffffffu, sr0[h], 1);
        sr0[h] += __shfl_xor_sync(0xffffffffu, sr0[h], 2);
        sl1[h] += __shfl_xor_sync(0xffffffffu, sl1[h], 1);
        sl1[h] += __shfl_xor_sync(0xffffffffu, sl1[h], 2);
        sr1[h] += __shfl_xor_sync(0xffffffffu, sr1[h], 1);
        sr1[h] += __shfl_xor_sync(0xffffffffu, sr1[h], 2);
    }
    if (qc == 0){
        int r0 = row0 + rw + qr;
        int r1 = r0 + 8;
        if (r0 < NN){
            #pragma unroll
            for (int h = 0; h < 4; h++){ g_el[r0*4+h] = sl0[h]; g_er[r0*4+h] = sr0[h]; }
        }
        if (r1 < NN){
            #pragma unroll
            for (int h = 0; h < 4; h++){ g_el[r1*4+h] = sl1[h]; g_er[r1*4+h] = sr1[h]; }
        }
    }
    __syncthreads();

    // ---- coalesced h writeback ----
    {
        float4* hd = (float4*)&g_h[(size_t)row0*DD];
        #pragma unroll 4
        for (int j = 0; j < 16; j++){
            int idx = j*256 + tid;
            int r = idx >> 5, c4 = idx & 31;
            hd[idx] = *(const float4*)&stagef[r*132 + c4*4];
        }
    }
}

// ---------------- fused edge-softmax + aggregation (warp per node) ---------
// self loop handled analytically (not in bucket). MODE: 0 = g_h gather,
// 1 = layer-0 rank-1 (el/er from weights inline), 2 = g_h + prediction head
template<int MODE>
__device__ __forceinline__ void smax_aggr_body(
    const float* __restrict__ bias, const float* __restrict__ weights,
    const float* __restrict__ pw, const float* __restrict__ pb,
    float* __restrict__ out)
{
    int wid = (blockIdx.x*blockDim.x + threadIdx.x) >> 5;
    if (wid >= NN) return;
    int lane = threadIdx.x & 31;
    int wd   = (threadIdx.x >> 5) & 7;
    __shared__ float sAlpha[8][128];
    __shared__ int   sSrc[8][32];

    int start = wid * BKT;
    int deg   = g_deg[wid];                  // excludes self
    if (deg > BKT) deg = BKT;

    // ---- phase 1: e + max (lanes over (edge,head)) ----
    int eh_e = lane >> 2;                    // edge slot within chunk (0..7)
    int eh_h = lane & 3;                     // head
    float wself, er_h, e_self;
    if (MODE == 1){
        wself = weights[wid];
        er_h  = wself*g_cr[eh_h] + g_dr[eh_h];
        e_self = lrelu02(wself*g_cl[eh_h] + g_dl[eh_h] + er_h);
    } else {
        wself = 0.f;
        er_h  = g_er[wid*4 + eh_h];
        e_self = lrelu02(g_el[wid*4 + eh_h] + er_h);
    }
    float ev[4];
    float mx = e_self;
    #pragma unroll
    for (int c = 0; c < 4; c++){
        int pi = c*8 + eh_e;
        float e = -3.0e38f;
        if (pi < deg){
            int s = g_csrc[start + pi];
            if (eh_h == 0) sSrc[wd][pi] = s;
            float els = (MODE == 1) ? (weights[s]*g_cl[eh_h] + g_dl[eh_h])
                                    : g_el[s*4 + eh_h];
            e = lrelu02(els + er_h);
        }
        ev[c] = e;
        mx = fmaxf(mx, e);
    }
    for (int pi = 32 + eh_e; pi < deg; pi += 8){          // rare overflow
        int s = g_csrc[start + pi];
        float els = (MODE == 1) ? (weights[s]*g_cl[eh_h] + g_dl[eh_h])
                                : g_el[s*4 + eh_h];
        mx = fmaxf(mx, lrelu02(els + er_h));
    }
    mx = fmaxf(mx, __shfl_xor_sync(0xffffffffu, mx, 4));
    mx = fmaxf(mx, __shfl_xor_sync(0xffffffffu, mx, 8));
    mx = fmaxf(mx, __shfl_xor_sync(0xffffffffu, mx, 16));

    // ---- phase 2: exp + sum ----
    float sum = (eh_e == 0) ? __expf(e_self - mx) : 0.f;
    #pragma unroll
    for (int c = 0; c < 4; c++){
        int pi = c*8 + eh_e;
        float a = 0.f;
        if (pi < deg) a = __expf(ev[c] - mx);
        ev[c] = a;
        sum += a;
    }
    for (int pi = 32 + eh_e; pi < deg; pi += 8){          // rare overflow
        int s = g_csrc[start + pi];
        float els = (MODE == 1) ? (weights[s]*g_cl[eh_h] + g_dl[eh_h])
                                : g_el[s*4 + eh_h];
        sum += __expf(lrelu02(els + er_h) - mx);
    }
    sum += __shfl_xor_sync(0xffffffffu, sum, 4);
    sum += __shfl_xor_sync(0xffffffffu, sum, 8);
    sum += __shfl_xor_sync(0xffffffffu, sum, 16);
    float invs = 1.0f / sum;

    #pragma unroll
    for (int c = 0; c < 4; c++){
        int pi = c*8 + eh_e;
        if (pi < deg && pi < 32) sAlpha[wd][pi*4 + eh_h] = ev[c]*invs;
    }
    __syncwarp();

    // ---- phase 3: aggregate over features (4x unrolled for MLP) ----
    int head = lane >> 3;
    float invs_h   = __shfl_sync(0xffffffffu, invs,   head);
    float mx_h     = __shfl_sync(0xffffffffu, mx,     head);
    float er_hh    = __shfl_sync(0xffffffffu, er_h,   head);
    float e_self_h = __shfl_sync(0xffffffffu, e_self, head);

    float4 acc = *(const float4*)&bias[lane*4];
    float4 c4, d4;
    if (MODE == 1){
        c4 = *(const float4*)&g_c[lane*4];
        d4 = *(const float4*)&g_d[lane*4];
    }
    // self contribution
    {
        float a_self = __expf(e_self_h - mx_h) * invs_h;
        if (MODE == 1){
            acc.x += (wself*c4.x + d4.x)*a_self;
            acc.y += (wself*c4.y + d4.y)*a_self;
            acc.z += (wself*c4.z + d4.z)*a_self;
            acc.w += (wself*c4.w + d4.w)*a_self;
        } else {
            float4 hv = *(const float4*)&g_h[(size_t)wid*DD + lane*4];
            acc.x += hv.x*a_self; acc.y += hv.y*a_self;
            acc.z += hv.z*a_self; acc.w += hv.w*a_self;
        }
    }
    int lim = deg < 32 ? deg : 32;
    int p = 0;
    for (; p + 4 <= lim; p += 4){
        int s0 = sSrc[wd][p],   s1 = sSrc[wd][p+1];
        int s2 = sSrc[wd][p+2], s3 = sSrc[wd][p+3];
        float w0 = sAlpha[wd][p*4 + head],     w1 = sAlpha[wd][(p+1)*4 + head];
        float w2 = sAlpha[wd][(p+2)*4 + head], w3 = sAlpha[wd][(p+3)*4 + head];
        if (MODE == 1){
            float ws0 = weights[s0], ws1 = weights[s1];
            float ws2 = weights[s2], ws3 = weights[s3];
            float wsum = w0 + w1 + w2 + w3;
            float wws  = ws0*w0 + ws1*w1 + ws2*w2 + ws3*w3;
            acc.x += wws*c4.x + wsum*d4.x;
            acc.y += wws*c4.y + wsum*d4.y;
            acc.z += wws*c4.z + wsum*d4.z;
            acc.w += wws*c4.w + wsum*d4.w;
        } else {
            float4 h0 = *(const float4*)&g_h[(size_t)s0*DD + lane*4];
            float4 h1 = *(const float4*)&g_h[(size_t)s1*DD + lane*4];
            float4 h2 = *(const float4*)&g_h[(size_t)s2*DD + lane*4];
            float4 h3 = *(const float4*)&g_h[(size_t)s3*DD + lane*4];
            acc.x += h0.x*w0 + h1.x*w1 + h2.x*w2 + h3.x*w3;
            acc.y += h0.y*w0 + h1.y*w1 + h2.y*w2 + h3.y*w3;
            acc.z += h0.z*w0 + h1.z*w1 + h2.z*w2 + h3.z*w3;
            acc.w += h0.w*w0 + h1.w*w1 + h2.w*w2 + h3.w*w3;
        }
    }
    for (; p < lim; p++){
        int s   = sSrc[wd][p];
        float w = sAlpha[wd][p*4 + head];
        if (MODE == 1){
            float ws = weights[s];
            acc.x += (ws*c4.x + d4.x)*w;
            acc.y += (ws*c4.y + d4.y)*w;
            acc.z += (ws*c4.z + d4.z)*w;
            acc.w += (ws*c4.w + d4.w)*w;
        } else {
            float4 hv = *(const float4*)&g_h[(size_t)s*DD + lane*4];
            acc.x += hv.x*w; acc.y += hv.y*w; acc.z += hv.z*w; acc.w += hv.w*w;
        }
    }
    for (p = 32; p < deg; p++){                           // rare overflow
        int s = g_csrc[start + p];
        float els = (MODE == 1) ? (weights[s]*g_cl[head] + g_dl[head])
                                : g_el[s*4 + head];
        float w = __expf(lrelu02(els + er_hh) - mx_h) * invs_h;
        if (MODE == 1){
            float ws = weights[s];
            acc.x += (ws*c4.x + d4.x)*w;
            acc.y += (ws*c4.y + d4.y)*w;
            acc.z += (ws*c4.z + d4.z)*w;
            acc.w += (ws*c4.w + d4.w)*w;
        } else {
            float4 hv = *(const float4*)&g_h[(size_t)s*DD + lane*4];
            acc.x += hv.x*w; acc.y += hv.y*w; acc.z += hv.z*w; acc.w += hv.w*w;
        }
    }

    if (MODE == 2){
        float4 wv = *(const float4*)&pw[lane*4];
        float sdot = acc.x*wv.x + acc.y*wv.y + acc.z*wv.z + acc.w*wv.w;
        #pragma unroll
        for (int o = 16; o; o >>= 1) sdot += __shfl_down_sync(0xffffffffu, sdot, o);
        if (lane == 0) out[wid] = sdot + pb[0];
    } else {
        *(float4*)&g_x[(size_t)wid*DD + lane*4] = acc;
    }
}

__global__ void k_smax_aggr(const float* __restrict__ bias){
    smax_aggr_body<0>(bias, nullptr, nullptr, nullptr, nullptr);
}
__global__ void k_smax_aggr0(const float* __restrict__ weights,
                             const float* __restrict__ bias){
    smax_aggr_body<1>(bias, weights, nullptr, nullptr, nullptr);
}
__global__ void k_smax_aggr_pred(const float* __restrict__ bias,
                                 const float* __restrict__ pw,
                                 const float* __restrict__ pb,
                                 float* __restrict__ out){
    smax_aggr_body<2>(bias, nullptr, pw, pb, out);
}

// ---------------- launch ----------------------------------------------------
// NOTE: never pass __device__ symbols as kernel arguments from host code —
// on GB300 (ATS) that silently binds the HOST shadow variable.
extern "C" void kernel_launch(void* const* d_in, const int* in_sizes, int n_in,
                              void* d_out, int out_size){
    const float* weights = (const float*)d_in[0];
    const float* lin_W   = (const float*)d_in[1];
    const float* lin_b   = (const float*)d_in[2];
    const float* fc_W    = (const float*)d_in[3];
    const float* attn_l  = (const float*)d_in[4];
    const float* attn_r  = (const float*)d_in[5];
    const float* conv_b  = (const float*)d_in[6];
    const float* pred_W  = (const float*)d_in[7];
    const float* pred_b  = (const float*)d_in[8];
    const int*   src     = (const int*)d_in[9];
    const int*   dst     = (const int*)d_in[10];
    float* out = (float*)d_out;

    static int smem_set = 0;
    if (!smem_set){
        cudaFuncSetAttribute(k_hgemm, cudaFuncAttributeMaxDynamicSharedMemorySize, SM_BYTES);
        smem_set = 1;
    }

    // --- bucket CSR build (no scans) + layer-0 prep fused into k_init ---
    k_init<<<(NN+255)/256, 256>>>(lin_W, lin_b, fc_W, attn_l, attn_r);
    k_fillbucket<<<(EE+255)/256, 256>>>(src, dst);

    // --- layer 0 (rank-1 features; el/er computed inline) ---
    k_smax_aggr0<<<(NN*32+255)/256, 256>>>(weights, conv_b);

    // --- layer 1 (HMMA GEMM fuses el/er epilogue) ---
    k_hgemm<<<NNP/128, 256, SM_BYTES>>>(fc_W + 1*DD*DD, attn_l + 1*DD, attn_r + 1*DD);
    k_smax_aggr<<<(NN*32+255)/256, 256>>>(conv_b + 1*DD);

    // --- layer 2 ---
    k_hgemm<<<NNP/128, 256, SM_BYTES>>>(fc_W + 2*DD*DD, attn_l + 2*DD, attn_r + 2*DD);
    k_smax_aggr_pred<<<(NN*32+255)/256, 256>>>(conv_b + 2*DD, pred_W, pred_b, out);
}